// round 6
// baseline (speedup 1.0000x reference)
#include <cuda_runtime.h>
#include <cstdint>

// Problem constants
#define BB   128
#define CIN  2
#define HIDC 150
#define AA   8
#define KIT  30
#define G    49
#define HP   51
#define GG   (G*G)      // 2401
#define HPHP (HP*HP)    // 2601
#define CPAD 160        // padded channel-last stride

// ---------------- scratch (device globals; 16B-aligned for vector access) ----
__device__ __align__(16) float g_hT  [BB*GG*CPAD];   // conv1 out, channel-last
__device__ __align__(16) float g_h2T [BB*GG*CPAD];   // conv2 out, channel-last
__device__ __align__(16) float g_tr  [BB*AA*9*HPHP]; // trans -> softmaxed in place
__device__ __align__(16) float g_rew [BB*HPHP];
__device__ __align__(16) float g_vbuf[2][BB*HPHP];
__device__ __align__(16) float g_q   [BB*AA*HPHP];
__device__ __align__(16) float g_wB2 [45*32*160];    // conv2 B tiles  [s][k][n], s=tap*5+cc
__device__ __align__(16) float g_wBrt[45*32*80];     // convrt B tiles [s][k][n]

// ============================ PTX helpers ====================================
__device__ __forceinline__ uint32_t smem_u32(const void* p) {
    uint32_t a;
    asm("{ .reg .u64 t; cvta.to.shared.u64 t, %1; cvt.u32.u64 %0, t; }" : "=r"(a) : "l"(p));
    return a;
}
__device__ __forceinline__ float to_tf32(float x) {
    uint32_t u;
    asm("cvt.rna.tf32.f32 %0, %1;" : "=r"(u) : "f"(x));
    return __uint_as_float(u);
}
__device__ __forceinline__ void cpa16(uint32_t dst, const void* src, uint32_t sz) {
    asm volatile("cp.async.cg.shared.global [%0], [%1], 16, %2;"
                 :: "r"(dst), "l"(src), "r"(sz) : "memory");
}
#define CP_COMMIT() asm volatile("cp.async.commit_group;" ::: "memory")
#define CP_WAIT1()  asm volatile("cp.async.wait_group 1;" ::: "memory")
#define CP_WAIT0()  asm volatile("cp.async.wait_group 0;" ::: "memory")
__device__ __forceinline__ void mma8(float* c, const uint32_t* a, const uint32_t* b) {
    asm volatile("mma.sync.aligned.m16n8k8.row.col.f32.tf32.tf32.f32 "
        "{%0,%1,%2,%3}, {%4,%5,%6,%7}, {%8,%9}, {%0,%1,%2,%3};"
        : "+f"(c[0]), "+f"(c[1]), "+f"(c[2]), "+f"(c[3])
        : "r"(a[0]), "r"(a[1]), "r"(a[2]), "r"(a[3]), "r"(b[0]), "r"(b[1]));
}

// ---------------- weight prep: build tf32 B tiles [s][k][n] ------------------
__global__ void prep_k(const float* __restrict__ h2w,
                       const float* __restrict__ rw,
                       const float* __restrict__ tw) {
    int i = blockIdx.x * blockDim.x + threadIdx.x;
    if (i < 45*32*160) {
        int n = i % 160, k = (i/160) % 32, s = i/(160*32);
        int tap = s/5, ci = (s%5)*32 + k;
        float v = 0.f;
        if (n < HIDC && ci < HIDC) v = h2w[(n*HIDC + ci)*9 + tap];
        g_wB2[i] = to_tf32(v);
    }
    if (i < 45*32*80) {
        int n = i % 80, k = (i/80) % 32, s = i/(80*32);
        int tap = s/5, ci = (s%5)*32 + k;
        float v = 0.f;
        if (ci < HIDC) {
            if (n == 0)      v = rw[ci*9 + tap];
            else if (n < 73) v = tw[((n-1)*HIDC + ci)*9 + tap];
        }
        g_wBrt[i] = to_tf32(v);
    }
}

// -------- conv1 fused with channel-last transpose: grid -> g_hT --------------
__global__ void conv1T_k(const float* __restrict__ gin,
                         const float* __restrict__ w,
                         const float* __restrict__ bias) {
    __shared__ float ws[HIDC*CIN*9];
    __shared__ float bs[HIDC];
    __shared__ __align__(16) float tile[32*164];
    int t = threadIdx.x;
    for (int i = t; i < HIDC*CIN*9; i += 256) ws[i] = w[i];
    for (int i = t; i < HIDC; i += 256) bs[i] = bias[i];
    __syncthreads();
    int pos0 = blockIdx.x * 32, b = blockIdx.y;
    int posi = t & 31, colane = t >> 5;
    int pos = pos0 + posi;
    bool okp = pos < GG;
    int y = okp ? pos / G : 0, x = okp ? pos % G : 0;
    float gv[CIN][9];
    #pragma unroll
    for (int ci = 0; ci < CIN; ci++)
        #pragma unroll
        for (int k = 0; k < 9; k++) {
            int r = y + k/3 - 1, c = x + k%3 - 1;
            gv[ci][k] = (okp && r >= 0 && r < G && c >= 0 && c < G)
                        ? gin[(b*CIN + ci)*GG + r*G + c] : 0.f;
        }
    #pragma unroll
    for (int j = 0; j < 19; j++) {
        int co = colane + 8*j;          // 0..151
        float out = 0.f;
        if (co < HIDC) {
            float acc = bs[co];
            #pragma unroll
            for (int ci = 0; ci < CIN; ci++)
                #pragma unroll
                for (int k = 0; k < 9; k++)
                    acc += gv[ci][k] * ws[(co*CIN + ci)*9 + k];
            out = to_tf32(fmaxf(acc, 0.f));
        }
        tile[posi*164 + co] = out;
    }
    if (t < 32)
        #pragma unroll
        for (int co = 152; co < CPAD; co++) tile[t*164 + co] = 0.f;
    __syncthreads();
    int p2 = t >> 3;
    if (pos0 + p2 < GG) {
        float4* op = (float4*)&g_hT[((size_t)(b*GG + pos0 + p2))*CPAD];
        #pragma unroll
        for (int i = 0; i < 5; i++) {
            int cq = (t & 7) + 8*i;
            op[cq] = *(float4*)&tile[p2*164 + cq*4];
        }
    }
}

// =============== tf32 mma.sync implicit-GEMM conv ============================
// ci-block outer, tap inner. Input patch (6 rows x WIN cols x 32ch) staged ONCE
// per ci-block; all 9 taps read it with a uniform smem offset. B double-buffered.
// MODE 0: conv2 (g_hT -> relu+bias -> g_h2T channel-last tf32), NFRAG=10 (N=160)
// MODE 1: convrt (g_h2T -> g_rew / g_tr), NFRAG=5 (N=80)
template<int NFRAG, int OW, int PADC, int PTOT, int MODE>
__global__ void __launch_bounds__(256, 2) mma_conv_k(const float* __restrict__ bias) {
    constexpr int NOUT_PAD = NFRAG * 16;
    constexpr int BPAD = NOUT_PAD + 8;
    constexpr int WIN  = OW + 2;          // smem patch width
    constexpr int ASZ  = 6 * WIN * 36;    // floats: 6 rows x WIN cols x 36-stride ch
    constexpr int BSZ  = 32 * BPAD;       // floats per B stage
    constexpr int AQ   = 6 * WIN * 8;     // 16B quads in A patch
    constexpr int BQ   = 32 * NOUT_PAD / 4;
    extern __shared__ __align__(16) float sm[];
    float* biasS = sm + ASZ + 2*BSZ;
    const float* inT = (MODE == 0) ? g_hT : g_h2T;
    const float* wB  = (MODE == 0) ? g_wB2 : g_wBrt;

    int t = threadIdx.x;
    int b = blockIdx.y, tile0 = blockIdx.x * 128;
    int y0 = tile0 / OW;
    uint32_t smb = smem_u32(sm);

    if (MODE == 0) for (int i = t; i < HIDC; i += 256) biasS[i] = bias[i];

    const int lane = t & 31, wid = t >> 5;
    const int gid = lane >> 2, tig = lane & 3;
    const int m0w = (wid >> 1) * 32, n0w = (wid & 1) * NFRAG * 8;

    // A fragment base offsets for this thread's 4 rows (mf in {0,1}, rr in {0,1})
    int baseA[2][2];
    #pragma unroll
    for (int mf = 0; mf < 2; mf++)
        #pragma unroll
        for (int rr = 0; rr < 2; rr++) {
            int pos = tile0 + m0w + mf*16 + rr*8 + gid;
            if (pos >= PTOT) pos = PTOT - 1;
            int y = pos / OW, x = pos - y*OW;
            baseA[mf][rr] = ((y - y0)*WIN + x)*36;
        }

    // loaders
    const float* inBase = inT + (size_t)b*GG*CPAD;
    auto load_A = [&](int cc) {
        #pragma unroll
        for (int j = 0; j < (AQ + 255)/256; j++) {
            int qi = t + 256*j;
            if (qi < AQ) {
                int q = qi & 7, rc = qi >> 3;
                int c = rc % WIN, jr = rc / WIN;
                int r_in = y0 - PADC + jr, gx = c - PADC;
                bool ok = ((unsigned)r_in < G) && ((unsigned)gx < G);
                const float* src = inBase + (size_t)(ok ? (r_in*G + gx) : 0)*CPAD + cc*32 + q*4;
                cpa16(smb + (uint32_t)((rc*36 + q*4)*4), src, ok ? 16u : 0u);
            }
        }
    };
    auto load_B = [&](int s, int stage) {
        uint32_t Bb = smb + (uint32_t)(ASZ + stage*BSZ)*4;
        const float* wsrc = wB + (size_t)s*32*NOUT_PAD;
        #pragma unroll
        for (int j = 0; j < (BQ + 255)/256; j++) {
            int q = t + 256*j;
            if (q < BQ) {
                int k = q / (NOUT_PAD/4), n4 = q - k*(NOUT_PAD/4);
                cpa16(Bb + (uint32_t)(k*BPAD + n4*4)*4, wsrc + q*4, 16u);
            }
        }
    };

    float c[2][NFRAG][4];
    #pragma unroll
    for (int mf = 0; mf < 2; mf++)
        #pragma unroll
        for (int nf = 0; nf < NFRAG; nf++)
            #pragma unroll
            for (int e = 0; e < 4; e++) c[mf][nf][e] = 0.f;

    for (int cc = 0; cc < 5; cc++) {
        __syncthreads();                 // prior ci-block fully consumed
        load_A(cc);
        load_B(0*5 + cc, 0);
        CP_COMMIT();
        for (int tap = 0; tap < 9; tap++) {
            int buf = tap & 1;
            if (tap < 8) { load_B((tap+1)*5 + cc, buf ^ 1); CP_COMMIT(); CP_WAIT1(); }
            else         { CP_WAIT0(); }
            __syncthreads();             // A(+B tap) visible to all warps
            int tapoff = ((tap/3)*WIN + (tap%3))*36;
            const float* As = sm;
            const float* Bs = sm + ASZ + buf*BSZ;
            #pragma unroll
            for (int ks = 0; ks < 4; ks++) {
                int kc = ks*8 + tig;
                uint32_t a[2][4];
                #pragma unroll
                for (int mf = 0; mf < 2; mf++) {
                    a[mf][0] = __float_as_uint(As[baseA[mf][0] + tapoff + kc]);
                    a[mf][1] = __float_as_uint(As[baseA[mf][1] + tapoff + kc]);
                    a[mf][2] = __float_as_uint(As[baseA[mf][0] + tapoff + kc + 4]);
                    a[mf][3] = __float_as_uint(As[baseA[mf][1] + tapoff + kc + 4]);
                }
                #pragma unroll
                for (int nf = 0; nf < NFRAG; nf++) {
                    int nc = n0w + nf*8 + gid;
                    uint32_t bv[2];
                    bv[0] = __float_as_uint(Bs[kc*BPAD + nc]);
                    bv[1] = __float_as_uint(Bs[(kc+4)*BPAD + nc]);
                    mma8(c[0][nf], a[0], bv);
                    mma8(c[1][nf], a[1], bv);
                }
            }
            __syncthreads();             // mma done before next B overwrite
        }
    }

    // ---- epilogue ----
    #pragma unroll
    for (int mf = 0; mf < 2; mf++) {
        #pragma unroll
        for (int rr = 0; rr < 2; rr++) {
            int pos = tile0 + m0w + mf*16 + gid + rr*8;
            if (pos >= PTOT) continue;
            if (MODE == 0) {
                float* op = &g_h2T[((size_t)(b*GG + pos))*CPAD];
                #pragma unroll
                for (int nf = 0; nf < NFRAG; nf++) {
                    int co = n0w + nf*8 + 2*tig;
                    float v0 = c[mf][nf][rr*2 + 0], v1 = c[mf][nf][rr*2 + 1];
                    float2 o;
                    o.x = (co   < HIDC) ? to_tf32(fmaxf(v0 + biasS[co],   0.f)) : 0.f;
                    o.y = (co+1 < HIDC) ? to_tf32(fmaxf(v1 + biasS[co+1], 0.f)) : 0.f;
                    *(float2*)&op[co] = o;
                }
            } else {
                #pragma unroll
                for (int nf = 0; nf < NFRAG; nf++) {
                    int co = n0w + nf*8 + 2*tig;
                    float v0 = c[mf][nf][rr*2 + 0], v1 = c[mf][nf][rr*2 + 1];
                    if (co == 0)      g_rew[b*HPHP + pos] = v0;
                    else if (co < 73) g_tr[((size_t)(b*72 + co - 1))*HPHP + pos] = v0;
                    if (co + 1 < 73)  g_tr[((size_t)(b*72 + co))*HPHP + pos] = v1;
                }
            }
        }
    }
}

// ---------------- softmax over 9 taps ---------------------------------------
__global__ void softmax_k() {
    int tid = blockIdx.x * blockDim.x + threadIdx.x;
    if (tid >= BB*AA*HPHP) return;
    int pos = tid % HPHP;
    int ba  = tid / HPHP;
    size_t base = (size_t)ba*9*HPHP + pos;
    float v[9];
    float m = -1e30f;
    #pragma unroll
    for (int k = 0; k < 9; k++) { v[k] = g_tr[base + (size_t)k*HPHP]; m = fmaxf(m, v[k]); }
    float s = 0.f;
    #pragma unroll
    for (int k = 0; k < 9; k++) { v[k] = expf(v[k] - m); s += v[k]; }
    float inv = 1.f / s;
    #pragma unroll
    for (int k = 0; k < 9; k++) g_tr[base + (size_t)k*HPHP] = v[k] * inv;
}

// ---------------- one value-iteration step ----------------------------------
__global__ void vi_step_k(int iter, int store_q) {
    int tid = blockIdx.x * blockDim.x + threadIdx.x;
    if (tid >= BB*HPHP) return;
    int b = tid / HPHP, pos = tid % HPHP, y = pos / HP, x = pos % HP;
    const float* vin = g_vbuf[(iter & 1) ^ 1];
    float p[9];
    if (iter == 0) {
        #pragma unroll
        for (int k = 0; k < 9; k++) p[k] = 0.f;
    } else {
        #pragma unroll
        for (int k = 0; k < 9; k++) {
            int r = y + k/3 - 1, c = x + k%3 - 1;
            p[k] = (r >= 0 && r < HP && c >= 0 && c < HP)
                   ? vin[b*HPHP + r*HP + c] : 0.f;
        }
    }
    float r0 = g_rew[tid];
    float vmax = -1e30f;
    #pragma unroll
    for (int a = 0; a < AA; a++) {
        size_t base = ((size_t)(b*72 + a*9))*HPHP + pos;
        float q = r0;
        #pragma unroll
        for (int k = 0; k < 9; k++) q += g_tr[base + (size_t)k*HPHP] * p[k];
        if (store_q) g_q[(b*AA + a)*HPHP + pos] = q;
        vmax = fmaxf(vmax, q);
    }
    g_vbuf[iter & 1][tid] = vmax;
}

// ---------------- head -------------------------------------------------------
__global__ void head_k(const float* __restrict__ a1w, const float* __restrict__ a1b,
                       const float* __restrict__ a2w, const float* __restrict__ a2b,
                       float* __restrict__ out) {
    __shared__ float a1s[HIDC*AA];
    __shared__ float a2s[AA*HIDC];
    __shared__ float b1s[HIDC];
    __shared__ float b2s[AA];
    int t = threadIdx.x;
    for (int i = t; i < HIDC*AA; i += blockDim.x) { a1s[i] = a1w[i]; a2s[i] = a2w[i]; }
    for (int i = t; i < HIDC; i += blockDim.x) b1s[i] = a1b[i];
    if (t < AA) b2s[t] = a2b[t];
    __syncthreads();
    int tid = blockIdx.x * blockDim.x + t;
    if (tid >= BB*GG) return;
    int b = tid / GG, pos = tid % GG, y = pos / G, x = pos % G;
    float qv[AA];
    #pragma unroll
    for (int a = 0; a < AA; a++) qv[a] = g_q[(b*AA + a)*HPHP + y*HP + x];
    float lg[AA];
    #pragma unroll
    for (int a = 0; a < AA; a++) lg[a] = 0.f;
    for (int c = 0; c < HIDC; c++) {
        float m = b1s[c];
        #pragma unroll
        for (int a = 0; a < AA; a++) m += qv[a] * a1s[c*AA + a];
        m = fmaxf(m, 0.f);
        #pragma unroll
        for (int a = 0; a < AA; a++) lg[a] += m * a2s[a*HIDC + c];
    }
    #pragma unroll
    for (int a = 0; a < AA; a++) out[(b*AA + a)*GG + pos] = lg[a] + b2s[a];
}

// ---------------- launch -----------------------------------------------------
extern "C" void kernel_launch(void* const* d_in, const int* in_sizes, int n_in,
                              void* d_out, int out_size) {
    const float* grid = (const float*)d_in[0];
    const float* h1w = (const float*)d_in[3];
    const float* h1b = (const float*)d_in[4];
    const float* h2w = (const float*)d_in[5];
    const float* h2b = (const float*)d_in[6];
    const float* rw  = (const float*)d_in[7];
    const float* tw  = (const float*)d_in[8];
    const float* a1w = (const float*)d_in[9];
    const float* a1b = (const float*)d_in[10];
    const float* a2w = (const float*)d_in[11];
    const float* a2b = (const float*)d_in[12];
    float* out = (float*)d_out;

    // dynamic smem: A(6*WIN*36) + 2*B(32*(N+8)) + bias
    const int SMEM2  = (6*51*36 + 2*32*168 + 160) * 4;   // 87712 B
    const int SMEMRT = (6*53*36 + 2*32*88  + 160) * 4;   // 68960 B
    cudaFuncSetAttribute(mma_conv_k<10, G, 1, GG, 0>,
                         cudaFuncAttributeMaxDynamicSharedMemorySize, SMEM2);
    cudaFuncSetAttribute(mma_conv_k<5, HP, 2, HPHP, 1>,
                         cudaFuncAttributeMaxDynamicSharedMemorySize, SMEMRT);

    prep_k<<<(45*32*160 + 255)/256, 256>>>(h2w, rw, tw);
    conv1T_k<<<dim3((GG + 31)/32, BB), 256>>>(grid, h1w, h1b);
    mma_conv_k<10, G, 1, GG, 0><<<dim3((GG + 127)/128, BB), 256, SMEM2>>>(h2b);
    mma_conv_k<5, HP, 2, HPHP, 1><<<dim3((HPHP + 127)/128, BB), 256, SMEMRT>>>(nullptr);
    softmax_k<<<(BB*AA*HPHP + 255)/256, 256>>>();
    for (int it = 0; it < KIT; it++)
        vi_step_k<<<(BB*HPHP + 255)/256, 256>>>(it, it == KIT - 1 ? 1 : 0);
    head_k<<<(BB*GG + 255)/256, 256>>>(a1w, a1b, a2w, a2b, out);
}

// round 7
// speedup vs baseline: 1.3865x; 1.3865x over previous
#include <cuda_runtime.h>
#include <cstdint>

// Problem constants
#define BB   128
#define CIN  2
#define HIDC 150
#define AA   8
#define KIT  30
#define G    49
#define HP   51
#define GG   (G*G)      // 2401
#define HPHP (HP*HP)    // 2601
#define CPAD 160        // padded channel-last stride

// ---------------- scratch (device globals; 16B-aligned for vector access) ----
__device__ __align__(16) float g_hT  [BB*GG*CPAD];   // conv1 out, channel-last
__device__ __align__(16) float g_h2T [BB*GG*CPAD];   // conv2 out, channel-last
__device__ __align__(16) float g_tr  [BB*AA*9*HPHP]; // trans -> softmaxed in place
__device__ __align__(16) float g_rew [BB*HPHP];
__device__ __align__(16) float g_vbuf[2][BB*HPHP];
__device__ __align__(16) float g_q   [BB*AA*HPHP];
__device__ __align__(16) float g_wB2 [45*32*160];    // conv2 B tiles  [s][k][n]
__device__ __align__(16) float g_wBrt[45*32*80];     // convrt B tiles [s][k][n]

// ============================ PTX helpers ====================================
__device__ __forceinline__ uint32_t smem_u32(const void* p) {
    uint32_t a;
    asm("{ .reg .u64 t; cvta.to.shared.u64 t, %1; cvt.u32.u64 %0, t; }" : "=r"(a) : "l"(p));
    return a;
}
__device__ __forceinline__ float to_tf32(float x) {
    uint32_t u;
    asm("cvt.rna.tf32.f32 %0, %1;" : "=r"(u) : "f"(x));
    return __uint_as_float(u);
}
__device__ __forceinline__ void cpa16(uint32_t dst, const void* src, uint32_t sz) {
    asm volatile("cp.async.cg.shared.global [%0], [%1], 16, %2;"
                 :: "r"(dst), "l"(src), "r"(sz) : "memory");
}
#define CP_COMMIT() asm volatile("cp.async.commit_group;" ::: "memory")
#define CP_WAIT1()  asm volatile("cp.async.wait_group 1;" ::: "memory")
#define CP_WAIT0()  asm volatile("cp.async.wait_group 0;" ::: "memory")
__device__ __forceinline__ void mma8(float* c, const uint32_t* a, const uint32_t* b) {
    asm volatile("mma.sync.aligned.m16n8k8.row.col.f32.tf32.tf32.f32 "
        "{%0,%1,%2,%3}, {%4,%5,%6,%7}, {%8,%9}, {%0,%1,%2,%3};"
        : "+f"(c[0]), "+f"(c[1]), "+f"(c[2]), "+f"(c[3])
        : "r"(a[0]), "r"(a[1]), "r"(a[2]), "r"(a[3]), "r"(b[0]), "r"(b[1]));
}

// ---------------- weight prep: build tf32 B tiles [s][k][n] ------------------
__global__ void prep_k(const float* __restrict__ h2w,
                       const float* __restrict__ rw,
                       const float* __restrict__ tw) {
    int i = blockIdx.x * blockDim.x + threadIdx.x;
    if (i < 45*32*160) {
        int n = i % 160, k = (i/160) % 32, s = i/(160*32);
        int tap = s/5, ci = (s%5)*32 + k;
        float v = 0.f;
        if (n < HIDC && ci < HIDC) v = h2w[(n*HIDC + ci)*9 + tap];
        g_wB2[i] = to_tf32(v);
    }
    if (i < 45*32*80) {
        int n = i % 80, k = (i/80) % 32, s = i/(80*32);
        int tap = s/5, ci = (s%5)*32 + k;
        float v = 0.f;
        if (ci < HIDC) {
            if (n == 0)      v = rw[ci*9 + tap];
            else if (n < 73) v = tw[((n-1)*HIDC + ci)*9 + tap];
        }
        g_wBrt[i] = to_tf32(v);
    }
}

// -------- conv1 fused with channel-last transpose: grid -> g_hT --------------
__global__ void conv1T_k(const float* __restrict__ gin,
                         const float* __restrict__ w,
                         const float* __restrict__ bias) {
    __shared__ float ws[HIDC*CIN*9];
    __shared__ float bs[HIDC];
    __shared__ __align__(16) float tile[32*164];
    int t = threadIdx.x;
    for (int i = t; i < HIDC*CIN*9; i += 256) ws[i] = w[i];
    for (int i = t; i < HIDC; i += 256) bs[i] = bias[i];
    __syncthreads();
    int pos0 = blockIdx.x * 32, b = blockIdx.y;
    int posi = t & 31, colane = t >> 5;
    int pos = pos0 + posi;
    bool okp = pos < GG;
    int y = okp ? pos / G : 0, x = okp ? pos % G : 0;
    float gv[CIN][9];
    #pragma unroll
    for (int ci = 0; ci < CIN; ci++)
        #pragma unroll
        for (int k = 0; k < 9; k++) {
            int r = y + k/3 - 1, c = x + k%3 - 1;
            gv[ci][k] = (okp && r >= 0 && r < G && c >= 0 && c < G)
                        ? gin[(b*CIN + ci)*GG + r*G + c] : 0.f;
        }
    #pragma unroll
    for (int j = 0; j < 19; j++) {
        int co = colane + 8*j;          // 0..151
        float out = 0.f;
        if (co < HIDC) {
            float acc = bs[co];
            #pragma unroll
            for (int ci = 0; ci < CIN; ci++)
                #pragma unroll
                for (int k = 0; k < 9; k++)
                    acc += gv[ci][k] * ws[(co*CIN + ci)*9 + k];
            out = to_tf32(fmaxf(acc, 0.f));
        }
        tile[posi*164 + co] = out;
    }
    if (t < 32)
        #pragma unroll
        for (int co = 152; co < CPAD; co++) tile[t*164 + co] = 0.f;
    __syncthreads();
    int p2 = t >> 3;
    if (pos0 + p2 < GG) {
        float4* op = (float4*)&g_hT[((size_t)(b*GG + pos0 + p2))*CPAD];
        #pragma unroll
        for (int i = 0; i < 5; i++) {
            int cq = (t & 7) + 8*i;
            op[cq] = *(float4*)&tile[p2*164 + cq*4];
        }
    }
}

// =============== tf32 mma.sync implicit-GEMM conv (R4 mainloop) ==============
// D[pos 128, co 80] = sum over 45 chunks (9 taps x 5 ci-blocks of 32).
// N=80 per CTA. MODE 0: conv2, N-split via blockIdx.z (0: co 0-79, 1: co 80-159),
//   writes relu+bias -> g_h2T channel-last tf32.
// MODE 1: convrt -> g_rew / g_tr.
template<int OW, int PADC, int PTOT, int MODE>
__global__ void __launch_bounds__(256, 3) mma_conv_k(const float* __restrict__ bias) {
    constexpr int NFRAG = 5;
    constexpr int NOUT_PAD = 80;
    constexpr int BPAD = 88;
    constexpr int ASZ = 128 * 36;         // floats per A stage
    constexpr int BSZ = 32 * BPAD;        // floats per B stage
    constexpr int BQ  = 32 * NOUT_PAD / 4; // 640
    constexpr int WST = (MODE == 0) ? 160 : 80;   // B source row stride
    extern __shared__ __align__(16) float sm[];
    float* biasS = sm + 2*ASZ + 2*BSZ;
    const float* inT = (MODE == 0) ? g_hT : g_h2T;
    const float* wB  = (MODE == 0) ? g_wB2 : g_wBrt;

    int t = threadIdx.x;
    int b = blockIdx.y, tile0 = blockIdx.x * 128;
    const int split = (MODE == 0) ? blockIdx.z : 0;
    uint32_t smb = smem_u32(sm);

    if (MODE == 0) for (int i = t; i < HIDC; i += 256) biasS[i] = bias[i];

    // A-load invariants: thread covers rows m = (t>>3)+32i, 16B quad cq = t&7
    const int cq = t & 7;
    int yy[4], xx[4];
    uint32_t dA[4];
    #pragma unroll
    for (int i = 0; i < 4; i++) {
        int m = (t >> 3) + 32*i;
        int pos = tile0 + m;
        yy[i] = pos / OW;
        xx[i] = pos - yy[i]*OW;
        dA[i] = (uint32_t)(m*36 + cq*4) * 4;
    }
    const float* inB = inT + (size_t)b*GG*CPAD + cq*4;

    auto load_chunk = [&](int s, int stage) {
        int tap = s / 5, cc = s - tap*5;
        int dyp = tap/3 - PADC, dxp = tap%3 - PADC, ci0 = cc*32;
        uint32_t Ab = smb + (uint32_t)stage*ASZ*4;
        #pragma unroll
        for (int i = 0; i < 4; i++) {
            int ir = yy[i] + dyp, ic = xx[i] + dxp;
            bool ok = ((unsigned)ir < G) && ((unsigned)ic < G);
            const float* src = inB + (size_t)(ok ? (ir*G + ic) : 0)*CPAD + ci0;
            cpa16(Ab + dA[i], src, ok ? 16u : 0u);
        }
        uint32_t Bb = smb + (uint32_t)(2*ASZ + stage*BSZ)*4;
        const float* wsrc = wB + (size_t)s*32*WST + split*80;
        #pragma unroll
        for (int j = 0; j < (BQ + 255)/256; j++) {
            int q = t + 256*j;
            if (q < BQ) {
                int k = q / (NOUT_PAD/4), n4 = q - k*(NOUT_PAD/4);
                cpa16(Bb + (uint32_t)(k*BPAD + n4*4)*4, wsrc + k*WST + n4*4, 16u);
            }
        }
        CP_COMMIT();
    };

    const int lane = t & 31, wid = t >> 5;
    const int gid = lane >> 2, tig = lane & 3;
    const int m0w = (wid >> 1) * 32, n0w = (wid & 1) * NFRAG * 8;

    float c[2][NFRAG][4];
    #pragma unroll
    for (int mf = 0; mf < 2; mf++)
        #pragma unroll
        for (int nf = 0; nf < NFRAG; nf++)
            #pragma unroll
            for (int e = 0; e < 4; e++) c[mf][nf][e] = 0.f;

    load_chunk(0, 0);
    for (int s = 0; s < 45; s++) {
        int cur = s & 1;
        if (s < 44) { load_chunk(s + 1, cur ^ 1); CP_WAIT1(); }
        else        { CP_WAIT0(); }
        __syncthreads();
        const float* As = sm + cur*ASZ;
        const float* Bs = sm + 2*ASZ + cur*BSZ;
        #pragma unroll
        for (int ks = 0; ks < 4; ks++) {
            int kc = ks*8 + tig;
            uint32_t a[2][4];
            #pragma unroll
            for (int mf = 0; mf < 2; mf++) {
                int r = m0w + mf*16 + gid;
                a[mf][0] = __float_as_uint(As[r*36 + kc]);
                a[mf][1] = __float_as_uint(As[(r+8)*36 + kc]);
                a[mf][2] = __float_as_uint(As[r*36 + kc + 4]);
                a[mf][3] = __float_as_uint(As[(r+8)*36 + kc + 4]);
            }
            #pragma unroll
            for (int nf = 0; nf < NFRAG; nf++) {
                int nc = n0w + nf*8 + gid;
                uint32_t bv[2];
                bv[0] = __float_as_uint(Bs[kc*BPAD + nc]);
                bv[1] = __float_as_uint(Bs[(kc+4)*BPAD + nc]);
                mma8(c[0][nf], a[0], bv);
                mma8(c[1][nf], a[1], bv);
            }
        }
        __syncthreads();
    }

    // ---- epilogue ----
    #pragma unroll
    for (int mf = 0; mf < 2; mf++) {
        #pragma unroll
        for (int rr = 0; rr < 2; rr++) {
            int pos = tile0 + m0w + mf*16 + gid + rr*8;
            if (pos >= PTOT) continue;
            if (MODE == 0) {
                float* op = &g_h2T[((size_t)(b*GG + pos))*CPAD];
                #pragma unroll
                for (int nf = 0; nf < NFRAG; nf++) {
                    int co = split*80 + n0w + nf*8 + 2*tig;
                    float v0 = c[mf][nf][rr*2 + 0], v1 = c[mf][nf][rr*2 + 1];
                    float2 o;
                    o.x = (co   < HIDC) ? to_tf32(fmaxf(v0 + biasS[co],   0.f)) : 0.f;
                    o.y = (co+1 < HIDC) ? to_tf32(fmaxf(v1 + biasS[co+1], 0.f)) : 0.f;
                    *(float2*)&op[co] = o;
                }
            } else {
                #pragma unroll
                for (int nf = 0; nf < NFRAG; nf++) {
                    int co = n0w + nf*8 + 2*tig;
                    float v0 = c[mf][nf][rr*2 + 0], v1 = c[mf][nf][rr*2 + 1];
                    if (co == 0)      g_rew[b*HPHP + pos] = v0;
                    else if (co < 73) g_tr[((size_t)(b*72 + co - 1))*HPHP + pos] = v0;
                    if (co + 1 < 73)  g_tr[((size_t)(b*72 + co))*HPHP + pos] = v1;
                }
            }
        }
    }
}

// ---------------- softmax over 9 taps ---------------------------------------
__global__ void softmax_k() {
    int tid = blockIdx.x * blockDim.x + threadIdx.x;
    if (tid >= BB*AA*HPHP) return;
    int pos = tid % HPHP;
    int ba  = tid / HPHP;
    size_t base = (size_t)ba*9*HPHP + pos;
    float v[9];
    float m = -1e30f;
    #pragma unroll
    for (int k = 0; k < 9; k++) { v[k] = g_tr[base + (size_t)k*HPHP]; m = fmaxf(m, v[k]); }
    float s = 0.f;
    #pragma unroll
    for (int k = 0; k < 9; k++) { v[k] = expf(v[k] - m); s += v[k]; }
    float inv = 1.f / s;
    #pragma unroll
    for (int k = 0; k < 9; k++) g_tr[base + (size_t)k*HPHP] = v[k] * inv;
}

// ---------------- one value-iteration step ----------------------------------
__global__ void vi_step_k(int iter, int store_q) {
    int tid = blockIdx.x * blockDim.x + threadIdx.x;
    if (tid >= BB*HPHP) return;
    int b = tid / HPHP, pos = tid % HPHP, y = pos / HP, x = pos % HP;
    const float* vin = g_vbuf[(iter & 1) ^ 1];
    float p[9];
    if (iter == 0) {
        #pragma unroll
        for (int k = 0; k < 9; k++) p[k] = 0.f;
    } else {
        #pragma unroll
        for (int k = 0; k < 9; k++) {
            int r = y + k/3 - 1, c = x + k%3 - 1;
            p[k] = (r >= 0 && r < HP && c >= 0 && c < HP)
                   ? vin[b*HPHP + r*HP + c] : 0.f;
        }
    }
    float r0 = g_rew[tid];
    float vmax = -1e30f;
    #pragma unroll
    for (int a = 0; a < AA; a++) {
        size_t base = ((size_t)(b*72 + a*9))*HPHP + pos;
        float q = r0;
        #pragma unroll
        for (int k = 0; k < 9; k++) q += g_tr[base + (size_t)k*HPHP] * p[k];
        if (store_q) g_q[(b*AA + a)*HPHP + pos] = q;
        vmax = fmaxf(vmax, q);
    }
    g_vbuf[iter & 1][tid] = vmax;
}

// ---------------- head -------------------------------------------------------
__global__ void head_k(const float* __restrict__ a1w, const float* __restrict__ a1b,
                       const float* __restrict__ a2w, const float* __restrict__ a2b,
                       float* __restrict__ out) {
    __shared__ float a1s[HIDC*AA];
    __shared__ float a2s[AA*HIDC];
    __shared__ float b1s[HIDC];
    __shared__ float b2s[AA];
    int t = threadIdx.x;
    for (int i = t; i < HIDC*AA; i += blockDim.x) { a1s[i] = a1w[i]; a2s[i] = a2w[i]; }
    for (int i = t; i < HIDC; i += blockDim.x) b1s[i] = a1b[i];
    if (t < AA) b2s[t] = a2b[t];
    __syncthreads();
    int tid = blockIdx.x * blockDim.x + t;
    if (tid >= BB*GG) return;
    int b = tid / GG, pos = tid % GG, y = pos / G, x = pos % G;
    float qv[AA];
    #pragma unroll
    for (int a = 0; a < AA; a++) qv[a] = g_q[(b*AA + a)*HPHP + y*HP + x];
    float lg[AA];
    #pragma unroll
    for (int a = 0; a < AA; a++) lg[a] = 0.f;
    for (int c = 0; c < HIDC; c++) {
        float m = b1s[c];
        #pragma unroll
        for (int a = 0; a < AA; a++) m += qv[a] * a1s[c*AA + a];
        m = fmaxf(m, 0.f);
        #pragma unroll
        for (int a = 0; a < AA; a++) lg[a] += m * a2s[a*HIDC + c];
    }
    #pragma unroll
    for (int a = 0; a < AA; a++) out[(b*AA + a)*GG + pos] = lg[a] + b2s[a];
}

// ---------------- launch -----------------------------------------------------
extern "C" void kernel_launch(void* const* d_in, const int* in_sizes, int n_in,
                              void* d_out, int out_size) {
    const float* grid = (const float*)d_in[0];
    const float* h1w = (const float*)d_in[3];
    const float* h1b = (const float*)d_in[4];
    const float* h2w = (const float*)d_in[5];
    const float* h2b = (const float*)d_in[6];
    const float* rw  = (const float*)d_in[7];
    const float* tw  = (const float*)d_in[8];
    const float* a1w = (const float*)d_in[9];
    const float* a1b = (const float*)d_in[10];
    const float* a2w = (const float*)d_in[11];
    const float* a2b = (const float*)d_in[12];
    float* out = (float*)d_out;

    // dynamic smem: 2*A(128x36) + 2*B(32x88) + bias = 60032 B -> 3 CTAs/SM
    const int SMEMC = (2*128*36 + 2*32*88 + 160) * 4;
    cudaFuncSetAttribute(mma_conv_k<G, 1, GG, 0>,
                         cudaFuncAttributeMaxDynamicSharedMemorySize, SMEMC);
    cudaFuncSetAttribute(mma_conv_k<HP, 2, HPHP, 1>,
                         cudaFuncAttributeMaxDynamicSharedMemorySize, SMEMC);

    prep_k<<<(45*32*160 + 255)/256, 256>>>(h2w, rw, tw);
    conv1T_k<<<dim3((GG + 31)/32, BB), 256>>>(grid, h1w, h1b);
    mma_conv_k<G, 1, GG, 0><<<dim3((GG + 127)/128, BB, 2), 256, SMEMC>>>(h2b);
    mma_conv_k<HP, 2, HPHP, 1><<<dim3((HPHP + 127)/128, BB, 1), 256, SMEMC>>>(nullptr);
    softmax_k<<<(BB*AA*HPHP + 255)/256, 256>>>();
    for (int it = 0; it < KIT; it++)
        vi_step_k<<<(BB*HPHP + 255)/256, 256>>>(it, it == KIT - 1 ? 1 : 0);
    head_k<<<(BB*GG + 255)/256, 256>>>(a1w, a1b, a2w, a2b, out);
}

// round 8
// speedup vs baseline: 1.4516x; 1.0470x over previous
#include <cuda_runtime.h>
#include <cstdint>

// Problem constants
#define BB   128
#define CIN  2
#define HIDC 150
#define AA   8
#define KIT  30
#define G    49
#define HP   51
#define GG   (G*G)      // 2401
#define HPHP (HP*HP)    // 2601
#define CPAD 160        // padded channel-last stride

// ---------------- scratch (device globals; 16B-aligned for vector access) ----
__device__ __align__(16) float g_hT  [BB*GG*CPAD];   // conv1 out, channel-last
__device__ __align__(16) float g_h2T [BB*GG*CPAD];   // conv2 out, channel-last
__device__ __align__(16) float g_tr  [BB*AA*9*HPHP]; // trans -> softmaxed in place
__device__ __align__(16) float g_rew [BB*HPHP];
__device__ __align__(16) float g_vbuf[2][BB*HPHP];
__device__ __align__(16) float g_q   [BB*AA*HPHP];
__device__ __align__(16) float g_wB2 [45*32*160];    // conv2 B tiles  [s][k][n]
__device__ __align__(16) float g_wBrt[45*32*80];     // convrt B tiles [s][k][n]

// ============================ PTX helpers ====================================
__device__ __forceinline__ uint32_t smem_u32(const void* p) {
    uint32_t a;
    asm("{ .reg .u64 t; cvta.to.shared.u64 t, %1; cvt.u32.u64 %0, t; }" : "=r"(a) : "l"(p));
    return a;
}
__device__ __forceinline__ float to_tf32(float x) {
    uint32_t u;
    asm("cvt.rna.tf32.f32 %0, %1;" : "=r"(u) : "f"(x));
    return __uint_as_float(u);
}
__device__ __forceinline__ void cpa16(uint32_t dst, const void* src, uint32_t sz) {
    asm volatile("cp.async.cg.shared.global [%0], [%1], 16, %2;"
                 :: "r"(dst), "l"(src), "r"(sz) : "memory");
}
#define CP_COMMIT() asm volatile("cp.async.commit_group;" ::: "memory")
#define CP_WAIT1()  asm volatile("cp.async.wait_group 1;" ::: "memory")
#define CP_WAIT0()  asm volatile("cp.async.wait_group 0;" ::: "memory")
__device__ __forceinline__ void mma8(float* c, const uint32_t* a, const uint32_t* b) {
    asm volatile("mma.sync.aligned.m16n8k8.row.col.f32.tf32.tf32.f32 "
        "{%0,%1,%2,%3}, {%4,%5,%6,%7}, {%8,%9}, {%0,%1,%2,%3};"
        : "+f"(c[0]), "+f"(c[1]), "+f"(c[2]), "+f"(c[3])
        : "r"(a[0]), "r"(a[1]), "r"(a[2]), "r"(a[3]), "r"(b[0]), "r"(b[1]));
}

// ---------------- weight prep: build tf32 B tiles [s][k][n] ------------------
__global__ void prep_k(const float* __restrict__ h2w,
                       const float* __restrict__ rw,
                       const float* __restrict__ tw) {
    int i = blockIdx.x * blockDim.x + threadIdx.x;
    if (i < 45*32*160) {
        int n = i % 160, k = (i/160) % 32, s = i/(160*32);
        int tap = s/5, ci = (s%5)*32 + k;
        float v = 0.f;
        if (n < HIDC && ci < HIDC) v = h2w[(n*HIDC + ci)*9 + tap];
        g_wB2[i] = to_tf32(v);
    }
    if (i < 45*32*80) {
        int n = i % 80, k = (i/80) % 32, s = i/(80*32);
        int tap = s/5, ci = (s%5)*32 + k;
        float v = 0.f;
        if (ci < HIDC) {
            if (n == 0)      v = rw[ci*9 + tap];
            else if (n < 73) v = tw[((n-1)*HIDC + ci)*9 + tap];
        }
        g_wBrt[i] = to_tf32(v);
    }
}

// -------- conv1 fused with channel-last transpose: grid -> g_hT --------------
__global__ void conv1T_k(const float* __restrict__ gin,
                         const float* __restrict__ w,
                         const float* __restrict__ bias) {
    __shared__ float ws[HIDC*CIN*9];
    __shared__ float bs[HIDC];
    __shared__ __align__(16) float tile[32*164];
    int t = threadIdx.x;
    for (int i = t; i < HIDC*CIN*9; i += 256) ws[i] = w[i];
    for (int i = t; i < HIDC; i += 256) bs[i] = bias[i];
    __syncthreads();
    int pos0 = blockIdx.x * 32, b = blockIdx.y;
    int posi = t & 31, colane = t >> 5;
    int pos = pos0 + posi;
    bool okp = pos < GG;
    int y = okp ? pos / G : 0, x = okp ? pos % G : 0;
    float gv[CIN][9];
    #pragma unroll
    for (int ci = 0; ci < CIN; ci++)
        #pragma unroll
        for (int k = 0; k < 9; k++) {
            int r = y + k/3 - 1, c = x + k%3 - 1;
            gv[ci][k] = (okp && r >= 0 && r < G && c >= 0 && c < G)
                        ? gin[(b*CIN + ci)*GG + r*G + c] : 0.f;
        }
    #pragma unroll
    for (int j = 0; j < 19; j++) {
        int co = colane + 8*j;          // 0..151
        float out = 0.f;
        if (co < HIDC) {
            float acc = bs[co];
            #pragma unroll
            for (int ci = 0; ci < CIN; ci++)
                #pragma unroll
                for (int k = 0; k < 9; k++)
                    acc += gv[ci][k] * ws[(co*CIN + ci)*9 + k];
            out = to_tf32(fmaxf(acc, 0.f));
        }
        tile[posi*164 + co] = out;
    }
    if (t < 32)
        #pragma unroll
        for (int co = 152; co < CPAD; co++) tile[t*164 + co] = 0.f;
    __syncthreads();
    int p2 = t >> 3;
    if (pos0 + p2 < GG) {
        float4* op = (float4*)&g_hT[((size_t)(b*GG + pos0 + p2))*CPAD];
        #pragma unroll
        for (int i = 0; i < 5; i++) {
            int cq = (t & 7) + 8*i;
            op[cq] = *(float4*)&tile[p2*164 + cq*4];
        }
    }
}

// =============== tf32 mma.sync implicit-GEMM conv (R4 + B swizzle) ===========
// D[pos 128, co NOUT_PAD] = sum over 45 chunks (9 taps x 5 ci-blocks of 32)
// B tile XOR-swizzled by 16B quad: quad (k, n4) stored at column n4 ^ (k&7).
// MODE 0: conv2 (g_hT -> relu+bias -> g_h2T channel-last tf32), NFRAG=10 (N=160)
// MODE 1: convrt (g_h2T -> g_rew / g_tr), NFRAG=5 (N=80)
template<int NFRAG, int OW, int PADC, int PTOT, int MODE, int MINB>
__global__ void __launch_bounds__(256, MINB) mma_conv_k(const float* __restrict__ bias) {
    constexpr int NOUT_PAD = NFRAG * 16;
    constexpr int NQ = NOUT_PAD / 4;                  // quads per B row (40 / 20)
    constexpr int BPAD = ((NQ + 7) & ~7) * 4;         // row stride: 160 / 96 floats
    constexpr int ASZ = 128 * 36;                     // floats per A stage
    constexpr int BSZ = 32 * BPAD;                    // floats per B stage
    constexpr int BQ  = 32 * NQ;                      // quads per B tile
    extern __shared__ __align__(16) float sm[];
    float* biasS = sm + 2*ASZ + 2*BSZ;
    const float* inT = (MODE == 0) ? g_hT : g_h2T;
    const float* wB  = (MODE == 0) ? g_wB2 : g_wBrt;

    int t = threadIdx.x;
    int b = blockIdx.y, tile0 = blockIdx.x * 128;
    uint32_t smb = smem_u32(sm);

    if (MODE == 0) for (int i = t; i < HIDC; i += 256) biasS[i] = bias[i];

    // A-load invariants: thread covers rows m = (t>>3)+32i, 16B quad cq = t&7
    const int cq = t & 7;
    int yy[4], xx[4];
    uint32_t dA[4];
    #pragma unroll
    for (int i = 0; i < 4; i++) {
        int m = (t >> 3) + 32*i;
        int pos = tile0 + m;
        yy[i] = pos / OW;
        xx[i] = pos - yy[i]*OW;
        dA[i] = (uint32_t)(m*36 + cq*4) * 4;
    }
    const float* inB = inT + (size_t)b*GG*CPAD + cq*4;

    auto load_chunk = [&](int s, int stage) {
        int tap = s / 5, cc = s - tap*5;
        int dyp = tap/3 - PADC, dxp = tap%3 - PADC, ci0 = cc*32;
        uint32_t Ab = smb + (uint32_t)stage*ASZ*4;
        #pragma unroll
        for (int i = 0; i < 4; i++) {
            int ir = yy[i] + dyp, ic = xx[i] + dxp;
            bool ok = ((unsigned)ir < G) && ((unsigned)ic < G);
            const float* src = inB + (size_t)(ok ? (ir*G + ic) : 0)*CPAD + ci0;
            cpa16(Ab + dA[i], src, ok ? 16u : 0u);
        }
        uint32_t Bb = smb + (uint32_t)(2*ASZ + stage*BSZ)*4;
        const float* wsrc = wB + (size_t)s*32*NOUT_PAD;
        #pragma unroll
        for (int j = 0; j < (BQ + 255)/256; j++) {
            int q = t + 256*j;
            if (q < BQ) {
                int k = q / NQ, n4 = q - k*NQ;
                int col = n4 ^ (k & 7);               // XOR swizzle
                cpa16(Bb + (uint32_t)(k*BPAD + col*4)*4, wsrc + q*4, 16u);
            }
        }
        CP_COMMIT();
    };

    const int lane = t & 31, wid = t >> 5;
    const int gid = lane >> 2, tig = lane & 3;
    const int m0w = (wid >> 1) * 32, n0w = (wid & 1) * NFRAG * 8;

    float c[2][NFRAG][4];
    #pragma unroll
    for (int mf = 0; mf < 2; mf++)
        #pragma unroll
        for (int nf = 0; nf < NFRAG; nf++)
            #pragma unroll
            for (int e = 0; e < 4; e++) c[mf][nf][e] = 0.f;

    load_chunk(0, 0);
    for (int s = 0; s < 45; s++) {
        int cur = s & 1;
        if (s < 44) { load_chunk(s + 1, cur ^ 1); CP_WAIT1(); }
        else        { CP_WAIT0(); }
        __syncthreads();
        const float* As = sm + cur*ASZ;
        const float* Bs = sm + 2*ASZ + cur*BSZ;
        #pragma unroll
        for (int ks = 0; ks < 4; ks++) {
            int kc = ks*8 + tig;
            uint32_t a[2][4];
            #pragma unroll
            for (int mf = 0; mf < 2; mf++) {
                int r = m0w + mf*16 + gid;
                a[mf][0] = __float_as_uint(As[r*36 + kc]);
                a[mf][1] = __float_as_uint(As[(r+8)*36 + kc]);
                a[mf][2] = __float_as_uint(As[r*36 + kc + 4]);
                a[mf][3] = __float_as_uint(As[(r+8)*36 + kc + 4]);
            }
            #pragma unroll
            for (int nf = 0; nf < NFRAG; nf++) {
                int nc = n0w + nf*8 + gid;
                int ncq = nc >> 2, ncr = nc & 3;
                uint32_t bv[2];
                bv[0] = __float_as_uint(Bs[kc*BPAD + ((ncq ^ tig) << 2) + ncr]);
                bv[1] = __float_as_uint(Bs[(kc+4)*BPAD + ((ncq ^ (tig+4)) << 2) + ncr]);
                mma8(c[0][nf], a[0], bv);
                mma8(c[1][nf], a[1], bv);
            }
        }
        __syncthreads();
    }

    // ---- epilogue ----
    #pragma unroll
    for (int mf = 0; mf < 2; mf++) {
        #pragma unroll
        for (int rr = 0; rr < 2; rr++) {
            int pos = tile0 + m0w + mf*16 + gid + rr*8;
            if (pos >= PTOT) continue;
            if (MODE == 0) {
                float* op = &g_h2T[((size_t)(b*GG + pos))*CPAD];
                #pragma unroll
                for (int nf = 0; nf < NFRAG; nf++) {
                    int co = n0w + nf*8 + 2*tig;
                    float v0 = c[mf][nf][rr*2 + 0], v1 = c[mf][nf][rr*2 + 1];
                    float2 o;
                    o.x = (co   < HIDC) ? to_tf32(fmaxf(v0 + biasS[co],   0.f)) : 0.f;
                    o.y = (co+1 < HIDC) ? to_tf32(fmaxf(v1 + biasS[co+1], 0.f)) : 0.f;
                    *(float2*)&op[co] = o;
                }
            } else {
                #pragma unroll
                for (int nf = 0; nf < NFRAG; nf++) {
                    int co = n0w + nf*8 + 2*tig;
                    float v0 = c[mf][nf][rr*2 + 0], v1 = c[mf][nf][rr*2 + 1];
                    if (co == 0)      g_rew[b*HPHP + pos] = v0;
                    else if (co < 73) g_tr[((size_t)(b*72 + co - 1))*HPHP + pos] = v0;
                    if (co + 1 < 73)  g_tr[((size_t)(b*72 + co))*HPHP + pos] = v1;
                }
            }
        }
    }
}

// ---------------- softmax over 9 taps ---------------------------------------
__global__ void softmax_k() {
    int tid = blockIdx.x * blockDim.x + threadIdx.x;
    if (tid >= BB*AA*HPHP) return;
    int pos = tid % HPHP;
    int ba  = tid / HPHP;
    size_t base = (size_t)ba*9*HPHP + pos;
    float v[9];
    float m = -1e30f;
    #pragma unroll
    for (int k = 0; k < 9; k++) { v[k] = g_tr[base + (size_t)k*HPHP]; m = fmaxf(m, v[k]); }
    float s = 0.f;
    #pragma unroll
    for (int k = 0; k < 9; k++) { v[k] = expf(v[k] - m); s += v[k]; }
    float inv = 1.f / s;
    #pragma unroll
    for (int k = 0; k < 9; k++) g_tr[base + (size_t)k*HPHP] = v[k] * inv;
}

// ---------------- one value-iteration step ----------------------------------
__global__ void vi_step_k(int iter, int store_q) {
    int tid = blockIdx.x * blockDim.x + threadIdx.x;
    if (tid >= BB*HPHP) return;
    int b = tid / HPHP, pos = tid % HPHP, y = pos / HP, x = pos % HP;
    const float* vin = g_vbuf[(iter & 1) ^ 1];
    float p[9];
    if (iter == 0) {
        #pragma unroll
        for (int k = 0; k < 9; k++) p[k] = 0.f;
    } else {
        #pragma unroll
        for (int k = 0; k < 9; k++) {
            int r = y + k/3 - 1, c = x + k%3 - 1;
            p[k] = (r >= 0 && r < HP && c >= 0 && c < HP)
                   ? vin[b*HPHP + r*HP + c] : 0.f;
        }
    }
    float r0 = g_rew[tid];
    float vmax = -1e30f;
    #pragma unroll
    for (int a = 0; a < AA; a++) {
        size_t base = ((size_t)(b*72 + a*9))*HPHP + pos;
        float q = r0;
        #pragma unroll
        for (int k = 0; k < 9; k++) q += g_tr[base + (size_t)k*HPHP] * p[k];
        if (store_q) g_q[(b*AA + a)*HPHP + pos] = q;
        vmax = fmaxf(vmax, q);
    }
    g_vbuf[iter & 1][tid] = vmax;
}

// ---------------- head -------------------------------------------------------
__global__ void head_k(const float* __restrict__ a1w, const float* __restrict__ a1b,
                       const float* __restrict__ a2w, const float* __restrict__ a2b,
                       float* __restrict__ out) {
    __shared__ float a1s[HIDC*AA];
    __shared__ float a2s[AA*HIDC];
    __shared__ float b1s[HIDC];
    __shared__ float b2s[AA];
    int t = threadIdx.x;
    for (int i = t; i < HIDC*AA; i += blockDim.x) { a1s[i] = a1w[i]; a2s[i] = a2w[i]; }
    for (int i = t; i < HIDC; i += blockDim.x) b1s[i] = a1b[i];
    if (t < AA) b2s[t] = a2b[t];
    __syncthreads();
    int tid = blockIdx.x * blockDim.x + t;
    if (tid >= BB*GG) return;
    int b = tid / GG, pos = tid % GG, y = pos / G, x = pos % G;
    float qv[AA];
    #pragma unroll
    for (int a = 0; a < AA; a++) qv[a] = g_q[(b*AA + a)*HPHP + y*HP + x];
    float lg[AA];
    #pragma unroll
    for (int a = 0; a < AA; a++) lg[a] = 0.f;
    for (int c = 0; c < HIDC; c++) {
        float m = b1s[c];
        #pragma unroll
        for (int a = 0; a < AA; a++) m += qv[a] * a1s[c*AA + a];
        m = fmaxf(m, 0.f);
        #pragma unroll
        for (int a = 0; a < AA; a++) lg[a] += m * a2s[a*HIDC + c];
    }
    #pragma unroll
    for (int a = 0; a < AA; a++) out[(b*AA + a)*GG + pos] = lg[a] + b2s[a];
}

// ---------------- launch -----------------------------------------------------
extern "C" void kernel_launch(void* const* d_in, const int* in_sizes, int n_in,
                              void* d_out, int out_size) {
    const float* grid = (const float*)d_in[0];
    const float* h1w = (const float*)d_in[3];
    const float* h1b = (const float*)d_in[4];
    const float* h2w = (const float*)d_in[5];
    const float* h2b = (const float*)d_in[6];
    const float* rw  = (const float*)d_in[7];
    const float* tw  = (const float*)d_in[8];
    const float* a1w = (const float*)d_in[9];
    const float* a1b = (const float*)d_in[10];
    const float* a2w = (const float*)d_in[11];
    const float* a2b = (const float*)d_in[12];
    float* out = (float*)d_out;

    // dynamic smem: 2*A(128x36) + 2*B(32xBPAD) + bias
    const int SMEM2  = (2*128*36 + 2*32*160 + 160) * 4;   // 78464 B
    const int SMEMRT = (2*128*36 + 2*32*96  + 160) * 4;   // 62080 B
    cudaFuncSetAttribute(mma_conv_k<10, G, 1, GG, 0, 2>,
                         cudaFuncAttributeMaxDynamicSharedMemorySize, SMEM2);
    cudaFuncSetAttribute(mma_conv_k<5, HP, 2, HPHP, 1, 3>,
                         cudaFuncAttributeMaxDynamicSharedMemorySize, SMEMRT);

    prep_k<<<(45*32*160 + 255)/256, 256>>>(h2w, rw, tw);
    conv1T_k<<<dim3((GG + 31)/32, BB), 256>>>(grid, h1w, h1b);
    mma_conv_k<10, G, 1, GG, 0, 2><<<dim3((GG + 127)/128, BB), 256, SMEM2>>>(h2b);
    mma_conv_k<5, HP, 2, HPHP, 1, 3><<<dim3((HPHP + 127)/128, BB), 256, SMEMRT>>>(nullptr);
    softmax_k<<<(BB*AA*HPHP + 255)/256, 256>>>();
    for (int it = 0; it < KIT; it++)
        vi_step_k<<<(BB*HPHP + 255)/256, 256>>>(it, it == KIT - 1 ? 1 : 0);
    head_k<<<(BB*GG + 255)/256, 256>>>(a1w, a1b, a2w, a2b, out);
}

// round 9
// speedup vs baseline: 1.4821x; 1.0210x over previous
#include <cuda_runtime.h>
#include <cstdint>

// Problem constants
#define BB   128
#define CIN  2
#define HIDC 150
#define AA   8
#define KIT  30
#define G    49
#define HP   51
#define GG   (G*G)      // 2401
#define HPHP (HP*HP)    // 2601
#define CPAD 160        // padded channel-last stride

// channel permutation within a 32-block: p = (b&3)*2 + ((b>>2)&1) + (b&24)
__host__ __device__ __forceinline__ int permc(int c) {
    int b = c & 31;
    return (c & ~31) | ((b & 3)*2 + ((b >> 2) & 1) + (b & 24));
}

// ---------------- scratch (device globals; 16B-aligned for vector access) ----
__device__ __align__(16) float g_hT  [BB*GG*CPAD];   // conv1 out, channel-last PERMUTED
__device__ __align__(16) float g_h2T [BB*GG*CPAD];   // conv2 out, channel-last PERMUTED
__device__ __align__(16) float g_tr  [BB*AA*9*HPHP]; // trans -> softmaxed in place
__device__ __align__(16) float g_rew [BB*HPHP];
__device__ __align__(16) float g_vbuf[2][BB*HPHP];
__device__ __align__(16) float g_q   [BB*AA*HPHP];
__device__ __align__(16) float g_wB2 [45*160*32];    // conv2 B tiles  [s][n][perm(k)]
__device__ __align__(16) float g_wBrt[45*80*32];     // convrt B tiles [s][n][perm(k)]

// ============================ PTX helpers ====================================
__device__ __forceinline__ uint32_t smem_u32(const void* p) {
    uint32_t a;
    asm("{ .reg .u64 t; cvta.to.shared.u64 t, %1; cvt.u32.u64 %0, t; }" : "=r"(a) : "l"(p));
    return a;
}
__device__ __forceinline__ float to_tf32(float x) {
    uint32_t u;
    asm("cvt.rna.tf32.f32 %0, %1;" : "=r"(u) : "f"(x));
    return __uint_as_float(u);
}
__device__ __forceinline__ void cpa16(uint32_t dst, const void* src, uint32_t sz) {
    asm volatile("cp.async.cg.shared.global [%0], [%1], 16, %2;"
                 :: "r"(dst), "l"(src), "r"(sz) : "memory");
}
#define CP_COMMIT() asm volatile("cp.async.commit_group;" ::: "memory")
#define CP_WAIT1()  asm volatile("cp.async.wait_group 1;" ::: "memory")
#define CP_WAIT0()  asm volatile("cp.async.wait_group 0;" ::: "memory")
__device__ __forceinline__ void mma8(float* c, const uint32_t* a, const uint32_t* b) {
    asm volatile("mma.sync.aligned.m16n8k8.row.col.f32.tf32.tf32.f32 "
        "{%0,%1,%2,%3}, {%4,%5,%6,%7}, {%8,%9}, {%0,%1,%2,%3};"
        : "+f"(c[0]), "+f"(c[1]), "+f"(c[2]), "+f"(c[3])
        : "r"(a[0]), "r"(a[1]), "r"(a[2]), "r"(a[3]), "r"(b[0]), "r"(b[1]));
}

// ---------------- weight prep: build tf32 B tiles [s][n][perm(k)] ------------
__global__ void prep_k(const float* __restrict__ h2w,
                       const float* __restrict__ rw,
                       const float* __restrict__ tw) {
    int i = blockIdx.x * blockDim.x + threadIdx.x;
    if (i < 45*160*32) {
        int pk = i & 31, n = (i >> 5) % 160, s = i / (160*32);
        int k = ((pk >> 1) & 1) | (((pk >> 2) & 1) << 1) | ((pk & 1) << 2) | (pk & 24);
        int tap = s/5, ci = (s%5)*32 + k;
        float v = 0.f;
        if (n < HIDC && ci < HIDC) v = h2w[(n*HIDC + ci)*9 + tap];
        g_wB2[i] = to_tf32(v);
    }
    if (i < 45*80*32) {
        int pk = i & 31, n = (i >> 5) % 80, s = i / (80*32);
        int k = ((pk >> 1) & 1) | (((pk >> 2) & 1) << 1) | ((pk & 1) << 2) | (pk & 24);
        int tap = s/5, ci = (s%5)*32 + k;
        float v = 0.f;
        if (ci < HIDC) {
            if (n == 0)      v = rw[ci*9 + tap];
            else if (n < 73) v = tw[((n-1)*HIDC + ci)*9 + tap];
        }
        g_wBrt[i] = to_tf32(v);
    }
}

// -------- conv1 fused with channel-last PERMUTED transpose: grid -> g_hT -----
__global__ void conv1T_k(const float* __restrict__ gin,
                         const float* __restrict__ w,
                         const float* __restrict__ bias) {
    __shared__ float ws[HIDC*CIN*9];
    __shared__ float bs[HIDC];
    __shared__ __align__(16) float tile[32*164];
    int t = threadIdx.x;
    for (int i = t; i < HIDC*CIN*9; i += 256) ws[i] = w[i];
    for (int i = t; i < HIDC; i += 256) bs[i] = bias[i];
    __syncthreads();
    int pos0 = blockIdx.x * 32, b = blockIdx.y;
    int posi = t & 31, colane = t >> 5;
    int pos = pos0 + posi;
    bool okp = pos < GG;
    int y = okp ? pos / G : 0, x = okp ? pos % G : 0;
    float gv[CIN][9];
    #pragma unroll
    for (int ci = 0; ci < CIN; ci++)
        #pragma unroll
        for (int k = 0; k < 9; k++) {
            int r = y + k/3 - 1, c = x + k%3 - 1;
            gv[ci][k] = (okp && r >= 0 && r < G && c >= 0 && c < G)
                        ? gin[(b*CIN + ci)*GG + r*G + c] : 0.f;
        }
    #pragma unroll
    for (int j = 0; j < 20; j++) {                  // co 0..159
        int co = colane + 8*j;
        float out = 0.f;
        if (co < HIDC) {
            float acc = bs[co];
            #pragma unroll
            for (int ci = 0; ci < CIN; ci++)
                #pragma unroll
                for (int k = 0; k < 9; k++)
                    acc += gv[ci][k] * ws[(co*CIN + ci)*9 + k];
            out = to_tf32(fmaxf(acc, 0.f));
        }
        tile[posi*164 + permc(co)] = out;           // bijective over 0..159
    }
    __syncthreads();
    int p2 = t >> 3;
    if (pos0 + p2 < GG) {
        float4* op = (float4*)&g_hT[((size_t)(b*GG + pos0 + p2))*CPAD];
        #pragma unroll
        for (int i = 0; i < 5; i++) {
            int cq = (t & 7) + 8*i;
            op[cq] = *(float4*)&tile[p2*164 + cq*4];
        }
    }
}

// =============== tf32 mma.sync implicit-GEMM conv (LDS.64 fragments) =========
// A smem: [m 128][pk 32] stride 40 (permuted channels, straight copy from gmem).
// B smem: [n NOUT_PAD][pk 32] stride 40 (from prep-permuted weights).
// Fragment pairs (k, k+4) are adjacent -> one LDS.64 each. Conflict-free.
// MODE 0: conv2 (g_hT -> relu+bias -> g_h2T permuted), NFRAG=10 (N=160)
// MODE 1: convrt (g_h2T -> g_rew / g_tr), NFRAG=5 (N=80)
template<int NFRAG, int OW, int PADC, int PTOT, int MODE, int MINB>
__global__ void __launch_bounds__(256, MINB) mma_conv_k(const float* __restrict__ bias) {
    constexpr int NOUT_PAD = NFRAG * 16;
    constexpr int ASTR = 40;
    constexpr int ASZ = 128 * ASTR;                 // 5120 floats/stage
    constexpr int BSZ = NOUT_PAD * ASTR;            // floats/stage
    constexpr int BQ  = NOUT_PAD * 8;               // 16B quads per B tile
    extern __shared__ __align__(16) float sm[];
    float* biasS = sm + 2*ASZ + 2*BSZ;
    const float* inT = (MODE == 0) ? g_hT : g_h2T;
    const float* wB  = (MODE == 0) ? g_wB2 : g_wBrt;

    int t = threadIdx.x;
    int b = blockIdx.y, tile0 = blockIdx.x * 128;
    uint32_t smb = smem_u32(sm);

    if (MODE == 0) for (int i = t; i < HIDC; i += 256) biasS[i] = bias[i];

    // A-load invariants: thread covers rows m = (t>>3)+32i, 16B quad cq = t&7
    const int cq = t & 7;
    int yy[4], xx[4];
    uint32_t dA[4];
    #pragma unroll
    for (int i = 0; i < 4; i++) {
        int m = (t >> 3) + 32*i;
        int pos = tile0 + m;
        yy[i] = pos / OW;
        xx[i] = pos - yy[i]*OW;
        dA[i] = (uint32_t)(m*ASTR + cq*4) * 4;
    }
    const float* inB = inT + (size_t)b*GG*CPAD + cq*4;

    auto load_chunk = [&](int s, int stage) {
        int tap = s / 5, cc = s - tap*5;
        int dyp = tap/3 - PADC, dxp = tap%3 - PADC, ci0 = cc*32;
        uint32_t Ab = smb + (uint32_t)stage*ASZ*4;
        #pragma unroll
        for (int i = 0; i < 4; i++) {
            int ir = yy[i] + dyp, ic = xx[i] + dxp;
            bool ok = ((unsigned)ir < G) && ((unsigned)ic < G);
            const float* src = inB + (size_t)(ok ? (ir*G + ic) : 0)*CPAD + ci0;
            cpa16(Ab + dA[i], src, ok ? 16u : 0u);
        }
        uint32_t Bb = smb + (uint32_t)(2*ASZ + stage*BSZ)*4;
        const float* wsrc = wB + (size_t)s*NOUT_PAD*32;
        #pragma unroll
        for (int j = 0; j < (BQ + 255)/256; j++) {
            int q = t + 256*j;
            if (q < BQ) {
                int n = q >> 3, jj = q & 7;
                cpa16(Bb + (uint32_t)(n*ASTR + jj*4)*4, wsrc + n*32 + jj*4, 16u);
            }
        }
        CP_COMMIT();
    };

    const int lane = t & 31, wid = t >> 5;
    const int gid = lane >> 2, tig = lane & 3;
    const int m0w = (wid >> 1) * 32, n0w = (wid & 1) * NFRAG * 8;

    float c[2][NFRAG][4];
    #pragma unroll
    for (int mf = 0; mf < 2; mf++)
        #pragma unroll
        for (int nf = 0; nf < NFRAG; nf++)
            #pragma unroll
            for (int e = 0; e < 4; e++) c[mf][nf][e] = 0.f;

    load_chunk(0, 0);
    for (int s = 0; s < 45; s++) {
        int cur = s & 1;
        if (s < 44) { load_chunk(s + 1, cur ^ 1); CP_WAIT1(); }
        else        { CP_WAIT0(); }
        __syncthreads();
        const float* As = sm + cur*ASZ;
        const float* Bs = sm + 2*ASZ + cur*BSZ;
        #pragma unroll
        for (int ks = 0; ks < 4; ks++) {
            const int koff = ks*8 + tig*2;          // perm(kc), perm(kc+4) adjacent
            uint32_t a[2][4];
            #pragma unroll
            for (int mf = 0; mf < 2; mf++) {
                int r = m0w + mf*16 + gid;
                float2 aLo = *(const float2*)&As[r*ASTR + koff];       // a0, a2
                float2 aHi = *(const float2*)&As[(r+8)*ASTR + koff];   // a1, a3
                a[mf][0] = __float_as_uint(aLo.x);
                a[mf][1] = __float_as_uint(aHi.x);
                a[mf][2] = __float_as_uint(aLo.y);
                a[mf][3] = __float_as_uint(aHi.y);
            }
            #pragma unroll
            for (int nf = 0; nf < NFRAG; nf++) {
                int nc = n0w + nf*8 + gid;
                float2 bv2 = *(const float2*)&Bs[nc*ASTR + koff];      // b0, b1
                uint32_t bv[2];
                bv[0] = __float_as_uint(bv2.x);
                bv[1] = __float_as_uint(bv2.y);
                mma8(c[0][nf], a[0], bv);
                mma8(c[1][nf], a[1], bv);
            }
        }
        __syncthreads();
    }

    // ---- epilogue ----
    #pragma unroll
    for (int mf = 0; mf < 2; mf++) {
        #pragma unroll
        for (int rr = 0; rr < 2; rr++) {
            int pos = tile0 + m0w + mf*16 + gid + rr*8;
            if (pos >= PTOT) continue;
            if (MODE == 0) {
                float* op = &g_h2T[((size_t)(b*GG + pos))*CPAD];
                #pragma unroll
                for (int nf = 0; nf < NFRAG; nf++) {
                    int co = n0w + nf*8 + 2*tig;
                    float v0 = c[mf][nf][rr*2 + 0], v1 = c[mf][nf][rr*2 + 1];
                    // permuted scalar stores (keeps activation layout consistent)
                    op[permc(co)]   = (co   < HIDC) ? to_tf32(fmaxf(v0 + biasS[co],   0.f)) : 0.f;
                    op[permc(co+1)] = (co+1 < HIDC) ? to_tf32(fmaxf(v1 + biasS[co+1], 0.f)) : 0.f;
                }
            } else {
                #pragma unroll
                for (int nf = 0; nf < NFRAG; nf++) {
                    int co = n0w + nf*8 + 2*tig;
                    float v0 = c[mf][nf][rr*2 + 0], v1 = c[mf][nf][rr*2 + 1];
                    if (co == 0)      g_rew[b*HPHP + pos] = v0;
                    else if (co < 73) g_tr[((size_t)(b*72 + co - 1))*HPHP + pos] = v0;
                    if (co + 1 < 73)  g_tr[((size_t)(b*72 + co))*HPHP + pos] = v1;
                }
            }
        }
    }
}

// ---------------- softmax over 9 taps ---------------------------------------
__global__ void softmax_k() {
    int tid = blockIdx.x * blockDim.x + threadIdx.x;
    if (tid >= BB*AA*HPHP) return;
    int pos = tid % HPHP;
    int ba  = tid / HPHP;
    size_t base = (size_t)ba*9*HPHP + pos;
    float v[9];
    float m = -1e30f;
    #pragma unroll
    for (int k = 0; k < 9; k++) { v[k] = g_tr[base + (size_t)k*HPHP]; m = fmaxf(m, v[k]); }
    float s = 0.f;
    #pragma unroll
    for (int k = 0; k < 9; k++) { v[k] = expf(v[k] - m); s += v[k]; }
    float inv = 1.f / s;
    #pragma unroll
    for (int k = 0; k < 9; k++) g_tr[base + (size_t)k*HPHP] = v[k] * inv;
}

// ---------------- one value-iteration step ----------------------------------
__global__ void vi_step_k(int iter, int store_q) {
    int tid = blockIdx.x * blockDim.x + threadIdx.x;
    if (tid >= BB*HPHP) return;
    int b = tid / HPHP, pos = tid % HPHP, y = pos / HP, x = pos % HP;
    const float* vin = g_vbuf[(iter & 1) ^ 1];
    float p[9];
    if (iter == 0) {
        #pragma unroll
        for (int k = 0; k < 9; k++) p[k] = 0.f;
    } else {
        #pragma unroll
        for (int k = 0; k < 9; k++) {
            int r = y + k/3 - 1, c = x + k%3 - 1;
            p[k] = (r >= 0 && r < HP && c >= 0 && c < HP)
                   ? vin[b*HPHP + r*HP + c] : 0.f;
        }
    }
    float r0 = g_rew[tid];
    float vmax = -1e30f;
    #pragma unroll
    for (int a = 0; a < AA; a++) {
        size_t base = ((size_t)(b*72 + a*9))*HPHP + pos;
        float q = r0;
        #pragma unroll
        for (int k = 0; k < 9; k++) q += g_tr[base + (size_t)k*HPHP] * p[k];
        if (store_q) g_q[(b*AA + a)*HPHP + pos] = q;
        vmax = fmaxf(vmax, q);
    }
    g_vbuf[iter & 1][tid] = vmax;
}

// ---------------- head -------------------------------------------------------
__global__ void head_k(const float* __restrict__ a1w, const float* __restrict__ a1b,
                       const float* __restrict__ a2w, const float* __restrict__ a2b,
                       float* __restrict__ out) {
    __shared__ float a1s[HIDC*AA];
    __shared__ float a2s[AA*HIDC];
    __shared__ float b1s[HIDC];
    __shared__ float b2s[AA];
    int t = threadIdx.x;
    for (int i = t; i < HIDC*AA; i += blockDim.x) { a1s[i] = a1w[i]; a2s[i] = a2w[i]; }
    for (int i = t; i < HIDC; i += blockDim.x) b1s[i] = a1b[i];
    if (t < AA) b2s[t] = a2b[t];
    __syncthreads();
    int tid = blockIdx.x * blockDim.x + t;
    if (tid >= BB*GG) return;
    int b = tid / GG, pos = tid % GG, y = pos / G, x = pos % G;
    float qv[AA];
    #pragma unroll
    for (int a = 0; a < AA; a++) qv[a] = g_q[(b*AA + a)*HPHP + y*HP + x];
    float lg[AA];
    #pragma unroll
    for (int a = 0; a < AA; a++) lg[a] = 0.f;
    for (int c = 0; c < HIDC; c++) {
        float m = b1s[c];
        #pragma unroll
        for (int a = 0; a < AA; a++) m += qv[a] * a1s[c*AA + a];
        m = fmaxf(m, 0.f);
        #pragma unroll
        for (int a = 0; a < AA; a++) lg[a] += m * a2s[a*HIDC + c];
    }
    #pragma unroll
    for (int a = 0; a < AA; a++) out[(b*AA + a)*GG + pos] = lg[a] + b2s[a];
}

// ---------------- launch -----------------------------------------------------
extern "C" void kernel_launch(void* const* d_in, const int* in_sizes, int n_in,
                              void* d_out, int out_size) {
    const float* grid = (const float*)d_in[0];
    const float* h1w = (const float*)d_in[3];
    const float* h1b = (const float*)d_in[4];
    const float* h2w = (const float*)d_in[5];
    const float* h2b = (const float*)d_in[6];
    const float* rw  = (const float*)d_in[7];
    const float* tw  = (const float*)d_in[8];
    const float* a1w = (const float*)d_in[9];
    const float* a1b = (const float*)d_in[10];
    const float* a2w = (const float*)d_in[11];
    const float* a2b = (const float*)d_in[12];
    float* out = (float*)d_out;

    // dynamic smem: 2*A(128x40) + 2*B(NOUT_PADx40) + bias
    const int SMEM2  = (2*128*40 + 2*160*40 + 160) * 4;   // 92800 B -> 2 CTAs/SM
    const int SMEMRT = (2*128*40 + 2*80*40  + 160) * 4;   // 67200 B -> 3 CTAs/SM
    cudaFuncSetAttribute(mma_conv_k<10, G, 1, GG, 0, 2>,
                         cudaFuncAttributeMaxDynamicSharedMemorySize, SMEM2);
    cudaFuncSetAttribute(mma_conv_k<5, HP, 2, HPHP, 1, 3>,
                         cudaFuncAttributeMaxDynamicSharedMemorySize, SMEMRT);

    prep_k<<<(45*160*32 + 255)/256, 256>>>(h2w, rw, tw);
    conv1T_k<<<dim3((GG + 31)/32, BB), 256>>>(grid, h1w, h1b);
    mma_conv_k<10, G, 1, GG, 0, 2><<<dim3((GG + 127)/128, BB), 256, SMEM2>>>(h2b);
    mma_conv_k<5, HP, 2, HPHP, 1, 3><<<dim3((HPHP + 127)/128, BB), 256, SMEMRT>>>(nullptr);
    softmax_k<<<(BB*AA*HPHP + 255)/256, 256>>>();
    for (int it = 0; it < KIT; it++)
        vi_step_k<<<(BB*HPHP + 255)/256, 256>>>(it, it == KIT - 1 ? 1 : 0);
    head_k<<<(BB*GG + 255)/256, 256>>>(a1w, a1b, a2w, a2b, out);
}

// round 10
// speedup vs baseline: 1.6749x; 1.1301x over previous
#include <cuda_runtime.h>
#include <cstdint>

// Problem constants
#define BB   128
#define CIN  2
#define HIDC 150
#define AA   8
#define KIT  30
#define G    49
#define HP   51
#define GG   (G*G)      // 2401
#define HPHP (HP*HP)    // 2601
#define CPAD 160        // padded channel-last stride

// channel permutation within a 32-block: pairs (k, k+4) become adjacent
__host__ __device__ __forceinline__ int permc(int c) {
    int b = c & 31;
    return (c & ~31) | ((b & 3)*2 + ((b >> 2) & 1) + (b & 24));
}

// ---------------- scratch (device globals; 16B-aligned) ----------------------
__device__ __align__(16) float g_hT  [BB*GG*CPAD];   // conv1 out, channel-last PERMUTED
__device__ __align__(16) float g_h2T [BB*GG*CPAD];   // conv2 out, channel-last UNPERMUTED
__device__ __align__(16) float g_tr  [BB*AA*9*HPHP]; // trans (fp32, pre-softmax src)
__device__ __align__(16) uint32_t g_tru[BB*9*4*HPHP];// softmaxed trans, u16 pairs [b][k][a2][pos]
__device__ __align__(16) float g_rew [BB*HPHP];
__device__ __align__(16) float g_vbuf[2][BB*HPHP];
__device__ __align__(16) float g_q   [BB*AA*HPHP];
__device__ __align__(16) float g_wB2 [45*160*32];    // conv2 B tiles  [s][n][perm(k)]
__device__ __align__(16) float g_wBrt[45*32*80];     // convrt B tiles [s][k][n]  (R4 layout)

// ============================ PTX helpers ====================================
__device__ __forceinline__ uint32_t smem_u32(const void* p) {
    uint32_t a;
    asm("{ .reg .u64 t; cvta.to.shared.u64 t, %1; cvt.u32.u64 %0, t; }" : "=r"(a) : "l"(p));
    return a;
}
__device__ __forceinline__ float to_tf32(float x) {
    uint32_t u;
    asm("cvt.rna.tf32.f32 %0, %1;" : "=r"(u) : "f"(x));
    return __uint_as_float(u);
}
__device__ __forceinline__ void cpa16(uint32_t dst, const void* src, uint32_t sz) {
    asm volatile("cp.async.cg.shared.global [%0], [%1], 16, %2;"
                 :: "r"(dst), "l"(src), "r"(sz) : "memory");
}
#define CP_COMMIT() asm volatile("cp.async.commit_group;" ::: "memory")
#define CP_WAIT1()  asm volatile("cp.async.wait_group 1;" ::: "memory")
#define CP_WAIT0()  asm volatile("cp.async.wait_group 0;" ::: "memory")
__device__ __forceinline__ void mma8(float* c, const uint32_t* a, const uint32_t* b) {
    asm volatile("mma.sync.aligned.m16n8k8.row.col.f32.tf32.tf32.f32 "
        "{%0,%1,%2,%3}, {%4,%5,%6,%7}, {%8,%9}, {%0,%1,%2,%3};"
        : "+f"(c[0]), "+f"(c[1]), "+f"(c[2]), "+f"(c[3])
        : "r"(a[0]), "r"(a[1]), "r"(a[2]), "r"(a[3]), "r"(b[0]), "r"(b[1]));
}

// ---------------- weight prep ------------------------------------------------
__global__ void prep_k(const float* __restrict__ h2w,
                       const float* __restrict__ rw,
                       const float* __restrict__ tw) {
    int i = blockIdx.x * blockDim.x + threadIdx.x;
    if (i < 45*160*32) {                     // conv2 weights [s][n][perm(k)]
        int pk = i & 31, n = (i >> 5) % 160, s = i / (160*32);
        int k = ((pk >> 1) & 1) | (((pk >> 2) & 1) << 1) | ((pk & 1) << 2) | (pk & 24);
        int tap = s/5, ci = (s%5)*32 + k;
        float v = 0.f;
        if (n < HIDC && ci < HIDC) v = h2w[(n*HIDC + ci)*9 + tap];
        g_wB2[i] = to_tf32(v);
    }
    if (i < 45*32*80) {                      // convrt weights [s][k][n] (R4)
        int n = i % 80, k = (i/80) % 32, s = i/(80*32);
        int tap = s/5, ci = (s%5)*32 + k;
        float v = 0.f;
        if (ci < HIDC) {
            if (n == 0)      v = rw[ci*9 + tap];
            else if (n < 73) v = tw[((n-1)*HIDC + ci)*9 + tap];
        }
        g_wBrt[i] = to_tf32(v);
    }
}

// -------- conv1 fused with channel-last PERMUTED transpose: grid -> g_hT -----
__global__ void conv1T_k(const float* __restrict__ gin,
                         const float* __restrict__ w,
                         const float* __restrict__ bias) {
    __shared__ float ws[HIDC*CIN*9];
    __shared__ float bs[HIDC];
    __shared__ __align__(16) float tile[32*164];
    int t = threadIdx.x;
    for (int i = t; i < HIDC*CIN*9; i += 256) ws[i] = w[i];
    for (int i = t; i < HIDC; i += 256) bs[i] = bias[i];
    __syncthreads();
    int pos0 = blockIdx.x * 32, b = blockIdx.y;
    int posi = t & 31, colane = t >> 5;
    int pos = pos0 + posi;
    bool okp = pos < GG;
    int y = okp ? pos / G : 0, x = okp ? pos % G : 0;
    float gv[CIN][9];
    #pragma unroll
    for (int ci = 0; ci < CIN; ci++)
        #pragma unroll
        for (int k = 0; k < 9; k++) {
            int r = y + k/3 - 1, c = x + k%3 - 1;
            gv[ci][k] = (okp && r >= 0 && r < G && c >= 0 && c < G)
                        ? gin[(b*CIN + ci)*GG + r*G + c] : 0.f;
        }
    #pragma unroll
    for (int j = 0; j < 20; j++) {
        int co = colane + 8*j;
        float out = 0.f;
        if (co < HIDC) {
            float acc = bs[co];
            #pragma unroll
            for (int ci = 0; ci < CIN; ci++)
                #pragma unroll
                for (int k = 0; k < 9; k++)
                    acc += gv[ci][k] * ws[(co*CIN + ci)*9 + k];
            out = to_tf32(fmaxf(acc, 0.f));
        }
        tile[posi*164 + permc(co)] = out;
    }
    __syncthreads();
    int p2 = t >> 3;
    if (pos0 + p2 < GG) {
        float4* op = (float4*)&g_hT[((size_t)(b*GG + pos0 + p2))*CPAD];
        #pragma unroll
        for (int i = 0; i < 5; i++) {
            int cq = (t & 7) + 8*i;
            op[cq] = *(float4*)&tile[p2*164 + cq*4];
        }
    }
}

// ============ conv2: LDS.64 fragments (perm input), R4 float2 epilogue =======
__global__ void __launch_bounds__(256, 2) conv2_mma_k(const float* __restrict__ bias) {
    constexpr int NFRAG = 10;
    constexpr int ASTR = 40;
    constexpr int ASZ = 128 * ASTR;
    constexpr int BSZ = 160 * ASTR;
    constexpr int BQ  = 160 * 8;
    extern __shared__ __align__(16) float sm[];
    float* biasS = sm + 2*ASZ + 2*BSZ;

    int t = threadIdx.x;
    int b = blockIdx.y, tile0 = blockIdx.x * 128;
    uint32_t smb = smem_u32(sm);
    for (int i = t; i < HIDC; i += 256) biasS[i] = bias[i];

    const int cq = t & 7;
    int yy[4], xx[4];
    uint32_t dA[4];
    #pragma unroll
    for (int i = 0; i < 4; i++) {
        int m = (t >> 3) + 32*i;
        int pos = tile0 + m;
        yy[i] = pos / G;
        xx[i] = pos - yy[i]*G;
        dA[i] = (uint32_t)(m*ASTR + cq*4) * 4;
    }
    const float* inB = g_hT + (size_t)b*GG*CPAD + cq*4;

    auto load_chunk = [&](int s, int stage) {
        int tap = s / 5, cc = s - tap*5;
        int dyp = tap/3 - 1, dxp = tap%3 - 1, ci0 = cc*32;
        uint32_t Ab = smb + (uint32_t)stage*ASZ*4;
        #pragma unroll
        for (int i = 0; i < 4; i++) {
            int ir = yy[i] + dyp, ic = xx[i] + dxp;
            bool ok = ((unsigned)ir < G) && ((unsigned)ic < G);
            const float* src = inB + (size_t)(ok ? (ir*G + ic) : 0)*CPAD + ci0;
            cpa16(Ab + dA[i], src, ok ? 16u : 0u);
        }
        uint32_t Bb = smb + (uint32_t)(2*ASZ + stage*BSZ)*4;
        const float* wsrc = g_wB2 + (size_t)s*160*32;
        #pragma unroll
        for (int j = 0; j < 5; j++) {
            int q = t + 256*j;
            if (q < BQ) {
                int n = q >> 3, jj = q & 7;
                cpa16(Bb + (uint32_t)(n*ASTR + jj*4)*4, wsrc + n*32 + jj*4, 16u);
            }
        }
        CP_COMMIT();
    };

    const int lane = t & 31, wid = t >> 5;
    const int gid = lane >> 2, tig = lane & 3;
    const int m0w = (wid >> 1) * 32, n0w = (wid & 1) * NFRAG * 8;

    float c[2][NFRAG][4];
    #pragma unroll
    for (int mf = 0; mf < 2; mf++)
        #pragma unroll
        for (int nf = 0; nf < NFRAG; nf++)
            #pragma unroll
            for (int e = 0; e < 4; e++) c[mf][nf][e] = 0.f;

    load_chunk(0, 0);
    for (int s = 0; s < 45; s++) {
        int cur = s & 1;
        if (s < 44) { load_chunk(s + 1, cur ^ 1); CP_WAIT1(); }
        else        { CP_WAIT0(); }
        __syncthreads();
        const float* As = sm + cur*ASZ;
        const float* Bs = sm + 2*ASZ + cur*BSZ;
        #pragma unroll
        for (int ks = 0; ks < 4; ks++) {
            const int koff = ks*8 + tig*2;
            uint32_t a[2][4];
            #pragma unroll
            for (int mf = 0; mf < 2; mf++) {
                int r = m0w + mf*16 + gid;
                float2 aLo = *(const float2*)&As[r*ASTR + koff];
                float2 aHi = *(const float2*)&As[(r+8)*ASTR + koff];
                a[mf][0] = __float_as_uint(aLo.x);
                a[mf][1] = __float_as_uint(aHi.x);
                a[mf][2] = __float_as_uint(aLo.y);
                a[mf][3] = __float_as_uint(aHi.y);
            }
            #pragma unroll
            for (int nf = 0; nf < NFRAG; nf++) {
                int nc = n0w + nf*8 + gid;
                float2 bv2 = *(const float2*)&Bs[nc*ASTR + koff];
                uint32_t bv[2];
                bv[0] = __float_as_uint(bv2.x);
                bv[1] = __float_as_uint(bv2.y);
                mma8(c[0][nf], a[0], bv);
                mma8(c[1][nf], a[1], bv);
            }
        }
        __syncthreads();
    }

    // R4-style float2 epilogue, UNPERMUTED g_h2T
    #pragma unroll
    for (int mf = 0; mf < 2; mf++) {
        #pragma unroll
        for (int rr = 0; rr < 2; rr++) {
            int pos = tile0 + m0w + mf*16 + gid + rr*8;
            if (pos >= GG) continue;
            float* op = &g_h2T[((size_t)(b*GG + pos))*CPAD];
            #pragma unroll
            for (int nf = 0; nf < NFRAG; nf++) {
                int co = n0w + nf*8 + 2*tig;
                float v0 = c[mf][nf][rr*2 + 0], v1 = c[mf][nf][rr*2 + 1];
                float2 o;
                o.x = (co   < HIDC) ? to_tf32(fmaxf(v0 + biasS[co],   0.f)) : 0.f;
                o.y = (co+1 < HIDC) ? to_tf32(fmaxf(v1 + biasS[co+1], 0.f)) : 0.f;
                *(float2*)&op[co] = o;
            }
        }
    }
}

// ============ convrt: R4-exact scalar-LDS mainloop ===========================
__global__ void __launch_bounds__(256, 3) convrt_mma_k() {
    constexpr int NFRAG = 5;
    constexpr int NOUT_PAD = 80;
    constexpr int BPAD = 88;
    constexpr int ASZ = 128 * 36;
    constexpr int BSZ = 32 * BPAD;
    constexpr int BQ  = 32 * NOUT_PAD / 4;
    extern __shared__ __align__(16) float sm[];

    int t = threadIdx.x;
    int b = blockIdx.y, tile0 = blockIdx.x * 128;
    uint32_t smb = smem_u32(sm);

    const int cq = t & 7;
    int yy[4], xx[4];
    uint32_t dA[4];
    #pragma unroll
    for (int i = 0; i < 4; i++) {
        int m = (t >> 3) + 32*i;
        int pos = tile0 + m;
        yy[i] = pos / HP;
        xx[i] = pos - yy[i]*HP;
        dA[i] = (uint32_t)(m*36 + cq*4) * 4;
    }
    const float* inB = g_h2T + (size_t)b*GG*CPAD + cq*4;

    auto load_chunk = [&](int s, int stage) {
        int tap = s / 5, cc = s - tap*5;
        int dyp = tap/3 - 2, dxp = tap%3 - 2, ci0 = cc*32;
        uint32_t Ab = smb + (uint32_t)stage*ASZ*4;
        #pragma unroll
        for (int i = 0; i < 4; i++) {
            int ir = yy[i] + dyp, ic = xx[i] + dxp;
            bool ok = ((unsigned)ir < G) && ((unsigned)ic < G);
            const float* src = inB + (size_t)(ok ? (ir*G + ic) : 0)*CPAD + ci0;
            cpa16(Ab + dA[i], src, ok ? 16u : 0u);
        }
        uint32_t Bb = smb + (uint32_t)(2*ASZ + stage*BSZ)*4;
        const float* wsrc = g_wBrt + (size_t)s*32*NOUT_PAD;
        #pragma unroll
        for (int j = 0; j < (BQ + 255)/256; j++) {
            int q = t + 256*j;
            if (q < BQ) {
                int k = q / (NOUT_PAD/4), n4 = q - k*(NOUT_PAD/4);
                cpa16(Bb + (uint32_t)(k*BPAD + n4*4)*4, wsrc + q*4, 16u);
            }
        }
        CP_COMMIT();
    };

    const int lane = t & 31, wid = t >> 5;
    const int gid = lane >> 2, tig = lane & 3;
    const int m0w = (wid >> 1) * 32, n0w = (wid & 1) * NFRAG * 8;

    float c[2][NFRAG][4];
    #pragma unroll
    for (int mf = 0; mf < 2; mf++)
        #pragma unroll
        for (int nf = 0; nf < NFRAG; nf++)
            #pragma unroll
            for (int e = 0; e < 4; e++) c[mf][nf][e] = 0.f;

    load_chunk(0, 0);
    for (int s = 0; s < 45; s++) {
        int cur = s & 1;
        if (s < 44) { load_chunk(s + 1, cur ^ 1); CP_WAIT1(); }
        else        { CP_WAIT0(); }
        __syncthreads();
        const float* As = sm + cur*ASZ;
        const float* Bs = sm + 2*ASZ + cur*BSZ;
        #pragma unroll
        for (int ks = 0; ks < 4; ks++) {
            int kc = ks*8 + tig;
            uint32_t a[2][4];
            #pragma unroll
            for (int mf = 0; mf < 2; mf++) {
                int r = m0w + mf*16 + gid;
                a[mf][0] = __float_as_uint(As[r*36 + kc]);
                a[mf][1] = __float_as_uint(As[(r+8)*36 + kc]);
                a[mf][2] = __float_as_uint(As[r*36 + kc + 4]);
                a[mf][3] = __float_as_uint(As[(r+8)*36 + kc + 4]);
            }
            #pragma unroll
            for (int nf = 0; nf < NFRAG; nf++) {
                int nc = n0w + nf*8 + gid;
                uint32_t bv[2];
                bv[0] = __float_as_uint(Bs[kc*BPAD + nc]);
                bv[1] = __float_as_uint(Bs[(kc+4)*BPAD + nc]);
                mma8(c[0][nf], a[0], bv);
                mma8(c[1][nf], a[1], bv);
            }
        }
        __syncthreads();
    }

    #pragma unroll
    for (int mf = 0; mf < 2; mf++) {
        #pragma unroll
        for (int rr = 0; rr < 2; rr++) {
            int pos = tile0 + m0w + mf*16 + gid + rr*8;
            if (pos >= HPHP) continue;
            #pragma unroll
            for (int nf = 0; nf < NFRAG; nf++) {
                int co = n0w + nf*8 + 2*tig;
                float v0 = c[mf][nf][rr*2 + 0], v1 = c[mf][nf][rr*2 + 1];
                if (co == 0)      g_rew[b*HPHP + pos] = v0;
                else if (co < 73) g_tr[((size_t)(b*72 + co - 1))*HPHP + pos] = v0;
                if (co + 1 < 73)  g_tr[((size_t)(b*72 + co))*HPHP + pos] = v1;
            }
        }
    }
}

// ------------- softmax over 9 taps -> u16 pairs (a, a+1) ---------------------
__global__ void softmax_k() {
    int tid = blockIdx.x * blockDim.x + threadIdx.x;
    if (tid >= BB*4*HPHP) return;
    int pos = tid % HPHP;
    int t2  = tid / HPHP;            // b*4 + a2
    int a2 = t2 & 3, b = t2 >> 2;
    size_t base0 = ((size_t)(b*8 + 2*a2))*9*HPHP + pos;
    float v0[9], v1[9];
    float m0 = -1e30f, m1 = -1e30f;
    #pragma unroll
    for (int k = 0; k < 9; k++) {
        v0[k] = g_tr[base0 + (size_t)k*HPHP];           m0 = fmaxf(m0, v0[k]);
        v1[k] = g_tr[base0 + (size_t)(9 + k)*HPHP];     m1 = fmaxf(m1, v1[k]);
    }
    float s0 = 0.f, s1 = 0.f;
    #pragma unroll
    for (int k = 0; k < 9; k++) {
        v0[k] = expf(v0[k] - m0); s0 += v0[k];
        v1[k] = expf(v1[k] - m1); s1 += v1[k];
    }
    float i0 = 65536.f / s0, i1 = 65536.f / s1;
    #pragma unroll
    for (int k = 0; k < 9; k++) {
        float y0 = fmaf(v0[k], i0, 8388608.f);
        float y1 = fmaf(v1[k], i1, 8388608.f);
        uint32_t pk = __byte_perm(__float_as_uint(y0), __float_as_uint(y1), 0x5410);
        g_tru[((size_t)(b*9 + k)*4 + a2)*HPHP + pos] = pk;
    }
}

// ---------------- one value-iteration step (u16 trans) -----------------------
__global__ void vi_step_k(int iter, int store_q) {
    int tid = blockIdx.x * blockDim.x + threadIdx.x;
    if (tid >= BB*HPHP) return;
    int b = tid / HPHP, pos = tid - b*HPHP, y = pos / HP, x = pos - y*HP;
    const float* vin = g_vbuf[(iter & 1) ^ 1];
    float p[9];
    if (iter == 0) {
        #pragma unroll
        for (int k = 0; k < 9; k++) p[k] = 0.f;
    } else {
        #pragma unroll
        for (int k = 0; k < 9; k++) {
            int r = y + k/3 - 1, c = x + k%3 - 1;
            p[k] = (r >= 0 && r < HP && c >= 0 && c < HP)
                   ? vin[b*HPHP + r*HP + c] : 0.f;
        }
    }
    float r0 = g_rew[tid];
    float vmax = -1e30f;
    const uint32_t* trb = g_tru + (size_t)b*36*HPHP + pos;
    #pragma unroll
    for (int a2 = 0; a2 < 4; a2++) {
        float q0 = r0, q1 = r0;
        #pragma unroll
        for (int k = 0; k < 9; k++) {
            uint32_t w = trb[(size_t)(k*4 + a2)*HPHP];
            float f0 = __uint_as_float(__byte_perm(w, 0x4B000000u, 0x7410));
            float f1 = __uint_as_float(__byte_perm(w, 0x4B000000u, 0x7432));
            float P0 = fmaf(f0, 1.f/65536.f, -128.f);   // exact u16/65536
            float P1 = fmaf(f1, 1.f/65536.f, -128.f);
            q0 = fmaf(P0, p[k], q0);
            q1 = fmaf(P1, p[k], q1);
        }
        if (store_q) {
            g_q[(b*AA + 2*a2    )*HPHP + pos] = q0;
            g_q[(b*AA + 2*a2 + 1)*HPHP + pos] = q1;
        }
        vmax = fmaxf(fmaxf(q0, q1), vmax);
    }
    g_vbuf[iter & 1][tid] = vmax;
}

// ---------------- head -------------------------------------------------------
__global__ void head_k(const float* __restrict__ a1w, const float* __restrict__ a1b,
                       const float* __restrict__ a2w, const float* __restrict__ a2b,
                       float* __restrict__ out) {
    __shared__ float a1s[HIDC*AA];
    __shared__ float a2s[AA*HIDC];
    __shared__ float b1s[HIDC];
    __shared__ float b2s[AA];
    int t = threadIdx.x;
    for (int i = t; i < HIDC*AA; i += blockDim.x) { a1s[i] = a1w[i]; a2s[i] = a2w[i]; }
    for (int i = t; i < HIDC; i += blockDim.x) b1s[i] = a1b[i];
    if (t < AA) b2s[t] = a2b[t];
    __syncthreads();
    int tid = blockIdx.x * blockDim.x + t;
    if (tid >= BB*GG) return;
    int b = tid / GG, pos = tid % GG, y = pos / G, x = pos % G;
    float qv[AA];
    #pragma unroll
    for (int a = 0; a < AA; a++) qv[a] = g_q[(b*AA + a)*HPHP + y*HP + x];
    float lg[AA];
    #pragma unroll
    for (int a = 0; a < AA; a++) lg[a] = 0.f;
    for (int c = 0; c < HIDC; c++) {
        float m = b1s[c];
        #pragma unroll
        for (int a = 0; a < AA; a++) m += qv[a] * a1s[c*AA + a];
        m = fmaxf(m, 0.f);
        #pragma unroll
        for (int a = 0; a < AA; a++) lg[a] += m * a2s[a*HIDC + c];
    }
    #pragma unroll
    for (int a = 0; a < AA; a++) out[(b*AA + a)*GG + pos] = lg[a] + b2s[a];
}

// ---------------- launch -----------------------------------------------------
extern "C" void kernel_launch(void* const* d_in, const int* in_sizes, int n_in,
                              void* d_out, int out_size) {
    const float* grid = (const float*)d_in[0];
    const float* h1w = (const float*)d_in[3];
    const float* h1b = (const float*)d_in[4];
    const float* h2w = (const float*)d_in[5];
    const float* h2b = (const float*)d_in[6];
    const float* rw  = (const float*)d_in[7];
    const float* tw  = (const float*)d_in[8];
    const float* a1w = (const float*)d_in[9];
    const float* a1b = (const float*)d_in[10];
    const float* a2w = (const float*)d_in[11];
    const float* a2b = (const float*)d_in[12];
    float* out = (float*)d_out;

    const int SMEM2  = (2*128*40 + 2*160*40 + 160) * 4;   // 92800 B -> 2 CTAs/SM
    const int SMEMRT = (2*128*36 + 2*32*88) * 4;          // 59392 B -> 3 CTAs/SM
    cudaFuncSetAttribute(conv2_mma_k,
                         cudaFuncAttributeMaxDynamicSharedMemorySize, SMEM2);
    cudaFuncSetAttribute(convrt_mma_k,
                         cudaFuncAttributeMaxDynamicSharedMemorySize, SMEMRT);

    prep_k<<<(45*160*32 + 255)/256, 256>>>(h2w, rw, tw);
    conv1T_k<<<dim3((GG + 31)/32, BB), 256>>>(grid, h1w, h1b);
    conv2_mma_k<<<dim3((GG + 127)/128, BB), 256, SMEM2>>>(h2b);
    convrt_mma_k<<<dim3((HPHP + 127)/128, BB), 256, SMEMRT>>>();
    softmax_k<<<(BB*4*HPHP + 255)/256, 256>>>();
    for (int it = 0; it < KIT; it++)
        vi_step_k<<<(BB*HPHP + 255)/256, 256>>>(it, it == KIT - 1 ? 1 : 0);
    head_k<<<(BB*GG + 255)/256, 256>>>(a1w, a1b, a2w, a2b, out);
}

// round 11
// speedup vs baseline: 2.4506x; 1.4631x over previous
#include <cuda_runtime.h>
#include <cuda_fp16.h>
#include <cstdint>

// Problem constants
#define BB   128
#define CIN  2
#define HIDC 150
#define AA   8
#define KIT  30
#define G    49
#define HP   51
#define GG   (G*G)      // 2401
#define HPHP (HP*HP)    // 2601
#define CPAD 160        // padded channel-last stride (halfs)

// ---------------- scratch (device globals; 16B-aligned) ----------------------
__device__ __align__(16) __half g_hT [BB*GG*CPAD];   // conv1 out, channel-last fp16
__device__ __align__(16) __half g_h2T[BB*GG*CPAD];   // conv2 out, channel-last fp16
__device__ __align__(16) float g_tr  [BB*AA*9*HPHP]; // trans (fp32, pre-softmax)
__device__ __align__(16) uint32_t g_tru[BB*9*4*HPHP];// softmaxed trans, u16 pairs
__device__ __align__(16) float g_rew [BB*HPHP];
__device__ __align__(16) float g_vbuf[2][BB*HPHP];
__device__ __align__(16) float g_q   [BB*AA*HPHP];
__device__ __align__(16) __half g_wB2 [45*160*32];   // conv2 B [s][n][k32] fp16
__device__ __align__(16) __half g_wBrt[45*80*32];    // convrt B [s][n][k32] fp16

// ============================ PTX helpers ====================================
__device__ __forceinline__ uint32_t smem_u32(const void* p) {
    uint32_t a;
    asm("{ .reg .u64 t; cvta.to.shared.u64 t, %1; cvt.u32.u64 %0, t; }" : "=r"(a) : "l"(p));
    return a;
}
__device__ __forceinline__ void cpa16(uint32_t dst, const void* src, uint32_t sz) {
    asm volatile("cp.async.cg.shared.global [%0], [%1], 16, %2;"
                 :: "r"(dst), "l"(src), "r"(sz) : "memory");
}
#define CP_COMMIT() asm volatile("cp.async.commit_group;" ::: "memory")
#define CP_WAIT1()  asm volatile("cp.async.wait_group 1;" ::: "memory")
#define CP_WAIT0()  asm volatile("cp.async.wait_group 0;" ::: "memory")
__device__ __forceinline__ void mma16(float* c, const uint32_t* a, const uint32_t* b) {
    asm volatile("mma.sync.aligned.m16n8k16.row.col.f32.f16.f16.f32 "
        "{%0,%1,%2,%3}, {%4,%5,%6,%7}, {%8,%9}, {%0,%1,%2,%3};"
        : "+f"(c[0]), "+f"(c[1]), "+f"(c[2]), "+f"(c[3])
        : "r"(a[0]), "r"(a[1]), "r"(a[2]), "r"(a[3]), "r"(b[0]), "r"(b[1]));
}

// ---------------- weight prep: fp16 B tiles [s][n][k(32)] --------------------
__global__ void prep_k(const float* __restrict__ h2w,
                       const float* __restrict__ rw,
                       const float* __restrict__ tw) {
    int i = blockIdx.x * blockDim.x + threadIdx.x;
    if (i < 45*160*32) {
        int k = i & 31, n = (i >> 5) % 160, s = i / (160*32);
        int tap = s/5, ci = (s%5)*32 + k;
        float v = 0.f;
        if (n < HIDC && ci < HIDC) v = h2w[(n*HIDC + ci)*9 + tap];
        g_wB2[i] = __float2half_rn(v);
    }
    if (i < 45*80*32) {
        int k = i & 31, n = (i >> 5) % 80, s = i / (80*32);
        int tap = s/5, ci = (s%5)*32 + k;
        float v = 0.f;
        if (ci < HIDC) {
            if (n == 0)      v = rw[ci*9 + tap];
            else if (n < 73) v = tw[((n-1)*HIDC + ci)*9 + tap];
        }
        g_wBrt[i] = __float2half_rn(v);
    }
}

// -------- conv1 fused with channel-last transpose: grid -> g_hT (fp16) -------
__global__ void conv1T_k(const float* __restrict__ gin,
                         const float* __restrict__ w,
                         const float* __restrict__ bias) {
    __shared__ float ws[HIDC*CIN*9];
    __shared__ float bs[HIDC];
    __shared__ __align__(16) __half tile[32*176];    // stride 176 halfs = 352B
    int t = threadIdx.x;
    for (int i = t; i < HIDC*CIN*9; i += 256) ws[i] = w[i];
    for (int i = t; i < HIDC; i += 256) bs[i] = bias[i];
    __syncthreads();
    int pos0 = blockIdx.x * 32, b = blockIdx.y;
    int posi = t & 31, colane = t >> 5;
    int pos = pos0 + posi;
    bool okp = pos < GG;
    int y = okp ? pos / G : 0, x = okp ? pos % G : 0;
    float gv[CIN][9];
    #pragma unroll
    for (int ci = 0; ci < CIN; ci++)
        #pragma unroll
        for (int k = 0; k < 9; k++) {
            int r = y + k/3 - 1, c = x + k%3 - 1;
            gv[ci][k] = (okp && r >= 0 && r < G && c >= 0 && c < G)
                        ? gin[(b*CIN + ci)*GG + r*G + c] : 0.f;
        }
    #pragma unroll
    for (int j = 0; j < 20; j++) {                    // co 0..159
        int co = colane + 8*j;
        float out = 0.f;
        if (co < HIDC) {
            float acc = bs[co];
            #pragma unroll
            for (int ci = 0; ci < CIN; ci++)
                #pragma unroll
                for (int k = 0; k < 9; k++)
                    acc += gv[ci][k] * ws[(co*CIN + ci)*9 + k];
            out = fmaxf(acc, 0.f);
        }
        tile[posi*176 + co] = __float2half_rn(out);
    }
    __syncthreads();
    // copy 32 rows x 160 halfs = 640 16B-quads
    #pragma unroll
    for (int j = 0; j < 3; j++) {
        int qi = t + 256*j;
        if (qi < 640) {
            int row = qi / 20, q = qi - row*20;
            if (pos0 + row < GG) {
                *(uint4*)&g_hT[((size_t)(b*GG + pos0 + row))*CPAD + q*8] =
                    *(const uint4*)&tile[row*176 + q*8];
            }
        }
    }
}

// =============== fp16 mma.sync m16n8k16 implicit-GEMM conv ===================
// A smem: [m 128][32 halfs] row stride 20 b32 (16 data + 4 pad). Conflict-free.
// B smem: [n NOUT_PAD][32 halfs] same stride.
// 45 chunks (tap x ci-block of 32 ch); 2 k-steps of 16 per chunk.
// MODE 0: conv2 (g_hT -> relu+bias -> g_h2T fp16), NFRAG=10 (N=160)
// MODE 1: convrt (g_h2T -> g_rew / g_tr fp32), NFRAG=5 (N=80)
template<int NFRAG, int OW, int PADC, int PTOT, int MODE, int MINB>
__global__ void __launch_bounds__(256, MINB) mma_conv_k(const float* __restrict__ bias) {
    constexpr int NOUT_PAD = NFRAG * 16;
    constexpr int RSTR = 20;                        // b32 per row
    constexpr int AW = 128 * RSTR;                  // b32 per A stage (2560)
    constexpr int BW = NOUT_PAD * RSTR;             // b32 per B stage
    constexpr int BQN = NOUT_PAD * 4;               // quads per B tile
    extern __shared__ __align__(16) uint32_t smu[];
    float* biasS = (float*)(smu + 2*AW + 2*BW);
    const __half* inH = (MODE == 0) ? g_hT : g_h2T;
    const __half* wB  = (MODE == 0) ? g_wB2 : g_wBrt;

    int t = threadIdx.x;
    int b = blockIdx.y, tile0 = blockIdx.x * 128;
    uint32_t smb = smem_u32(smu);

    if (MODE == 0) for (int i = t; i < HIDC; i += 256) biasS[i] = bias[i];

    // A-load invariants: thread covers rows (t>>2) and (t>>2)+64, quad t&3
    const int aq = t & 3;
    int yy[2], xx[2];
    uint32_t dA[2];
    #pragma unroll
    for (int i = 0; i < 2; i++) {
        int row = (t >> 2) + 64*i;
        int pos = tile0 + row;
        yy[i] = pos / OW;
        xx[i] = pos - yy[i]*OW;
        dA[i] = (uint32_t)(row*RSTR*4 + aq*16);
    }
    const __half* inB = inH + (size_t)b*GG*CPAD + aq*8;

    auto load_chunk = [&](int s, int stage) {
        int tap = s / 5, cc = s - tap*5;
        int dyp = tap/3 - PADC, dxp = tap%3 - PADC, ci0 = cc*32;
        uint32_t Ab = smb + (uint32_t)stage*AW*4;
        #pragma unroll
        for (int i = 0; i < 2; i++) {
            int ir = yy[i] + dyp, ic = xx[i] + dxp;
            bool ok = ((unsigned)ir < G) && ((unsigned)ic < G);
            const __half* src = inB + (size_t)(ok ? (ir*G + ic) : 0)*CPAD + ci0;
            cpa16(Ab + dA[i], src, ok ? 16u : 0u);
        }
        uint32_t Bb = smb + (uint32_t)(2*AW + stage*BW)*4;
        const __half* wsrc = wB + (size_t)s*NOUT_PAD*32;
        #pragma unroll
        for (int j = 0; j < (BQN + 255)/256; j++) {
            int qi = t + 256*j;
            if (qi < BQN) {
                int n = qi >> 2, q = qi & 3;
                cpa16(Bb + (uint32_t)(n*RSTR*4 + q*16), wsrc + n*32 + q*8, 16u);
            }
        }
        CP_COMMIT();
    };

    const int lane = t & 31, wid = t >> 5;
    const int gid = lane >> 2, tig = lane & 3;
    const int m0w = (wid >> 1) * 32, n0w = (wid & 1) * NFRAG * 8;

    float c[2][NFRAG][4];
    #pragma unroll
    for (int mf = 0; mf < 2; mf++)
        #pragma unroll
        for (int nf = 0; nf < NFRAG; nf++)
            #pragma unroll
            for (int e = 0; e < 4; e++) c[mf][nf][e] = 0.f;

    load_chunk(0, 0);
    for (int s = 0; s < 45; s++) {
        int cur = s & 1;
        if (s < 44) { load_chunk(s + 1, cur ^ 1); CP_WAIT1(); }
        else        { CP_WAIT0(); }
        __syncthreads();
        const uint32_t* As = smu + cur*AW;
        const uint32_t* Bs = smu + 2*AW + cur*BW;
        #pragma unroll
        for (int ks = 0; ks < 2; ks++) {
            int koff = ks*8 + tig;
            uint32_t a[2][4];
            #pragma unroll
            for (int mf = 0; mf < 2; mf++) {
                int r = m0w + mf*16 + gid;
                a[mf][0] = As[r*RSTR + koff];
                a[mf][1] = As[(r+8)*RSTR + koff];
                a[mf][2] = As[r*RSTR + koff + 4];
                a[mf][3] = As[(r+8)*RSTR + koff + 4];
            }
            #pragma unroll
            for (int nf = 0; nf < NFRAG; nf++) {
                int nc = n0w + nf*8 + gid;
                uint32_t bv[2];
                bv[0] = Bs[nc*RSTR + koff];
                bv[1] = Bs[nc*RSTR + koff + 4];
                mma16(c[0][nf], a[0], bv);
                mma16(c[1][nf], a[1], bv);
            }
        }
        __syncthreads();
    }

    // ---- epilogue ----
    #pragma unroll
    for (int mf = 0; mf < 2; mf++) {
        #pragma unroll
        for (int rr = 0; rr < 2; rr++) {
            int pos = tile0 + m0w + mf*16 + gid + rr*8;
            if (pos >= PTOT) continue;
            if (MODE == 0) {
                __half* op = &g_h2T[((size_t)(b*GG + pos))*CPAD];
                #pragma unroll
                for (int nf = 0; nf < NFRAG; nf++) {
                    int co = n0w + nf*8 + 2*tig;
                    float v0 = c[mf][nf][rr*2 + 0], v1 = c[mf][nf][rr*2 + 1];
                    float o0 = (co   < HIDC) ? fmaxf(v0 + biasS[co],   0.f) : 0.f;
                    float o1 = (co+1 < HIDC) ? fmaxf(v1 + biasS[co+1], 0.f) : 0.f;
                    *(__half2*)&op[co] = __floats2half2_rn(o0, o1);
                }
            } else {
                #pragma unroll
                for (int nf = 0; nf < NFRAG; nf++) {
                    int co = n0w + nf*8 + 2*tig;
                    float v0 = c[mf][nf][rr*2 + 0], v1 = c[mf][nf][rr*2 + 1];
                    if (co == 0)      g_rew[b*HPHP + pos] = v0;
                    else if (co < 73) g_tr[((size_t)(b*72 + co - 1))*HPHP + pos] = v0;
                    if (co + 1 < 73)  g_tr[((size_t)(b*72 + co))*HPHP + pos] = v1;
                }
            }
        }
    }
}

// ------------- softmax over 9 taps -> u16 pairs (a, a+1) ---------------------
__global__ void softmax_k() {
    int tid = blockIdx.x * blockDim.x + threadIdx.x;
    if (tid >= BB*4*HPHP) return;
    int pos = tid % HPHP;
    int t2  = tid / HPHP;
    int a2 = t2 & 3, b = t2 >> 2;
    size_t base0 = ((size_t)(b*8 + 2*a2))*9*HPHP + pos;
    float v0[9], v1[9];
    float m0 = -1e30f, m1 = -1e30f;
    #pragma unroll
    for (int k = 0; k < 9; k++) {
        v0[k] = g_tr[base0 + (size_t)k*HPHP];           m0 = fmaxf(m0, v0[k]);
        v1[k] = g_tr[base0 + (size_t)(9 + k)*HPHP];     m1 = fmaxf(m1, v1[k]);
    }
    float s0 = 0.f, s1 = 0.f;
    #pragma unroll
    for (int k = 0; k < 9; k++) {
        v0[k] = expf(v0[k] - m0); s0 += v0[k];
        v1[k] = expf(v1[k] - m1); s1 += v1[k];
    }
    float i0 = 65536.f / s0, i1 = 65536.f / s1;
    #pragma unroll
    for (int k = 0; k < 9; k++) {
        float y0 = fmaf(v0[k], i0, 8388608.f);
        float y1 = fmaf(v1[k], i1, 8388608.f);
        uint32_t pk = __byte_perm(__float_as_uint(y0), __float_as_uint(y1), 0x5410);
        g_tru[((size_t)(b*9 + k)*4 + a2)*HPHP + pos] = pk;
    }
}

// ---------------- one value-iteration step (u16 trans) -----------------------
__global__ void vi_step_k(int iter, int store_q) {
    int tid = blockIdx.x * blockDim.x + threadIdx.x;
    if (tid >= BB*HPHP) return;
    int b = tid / HPHP, pos = tid - b*HPHP, y = pos / HP, x = pos - y*HP;
    const float* vin = g_vbuf[(iter & 1) ^ 1];
    float p[9];
    if (iter == 0) {
        #pragma unroll
        for (int k = 0; k < 9; k++) p[k] = 0.f;
    } else {
        #pragma unroll
        for (int k = 0; k < 9; k++) {
            int r = y + k/3 - 1, c = x + k%3 - 1;
            p[k] = (r >= 0 && r < HP && c >= 0 && c < HP)
                   ? vin[b*HPHP + r*HP + c] : 0.f;
        }
    }
    float r0 = g_rew[tid];
    float vmax = -1e30f;
    const uint32_t* trb = g_tru + (size_t)b*36*HPHP + pos;
    #pragma unroll
    for (int a2 = 0; a2 < 4; a2++) {
        float q0 = r0, q1 = r0;
        #pragma unroll
        for (int k = 0; k < 9; k++) {
            uint32_t w = trb[(size_t)(k*4 + a2)*HPHP];
            float f0 = __uint_as_float(__byte_perm(w, 0x4B000000u, 0x7410));
            float f1 = __uint_as_float(__byte_perm(w, 0x4B000000u, 0x7432));
            float P0 = fmaf(f0, 1.f/65536.f, -128.f);
            float P1 = fmaf(f1, 1.f/65536.f, -128.f);
            q0 = fmaf(P0, p[k], q0);
            q1 = fmaf(P1, p[k], q1);
        }
        if (store_q) {
            g_q[(b*AA + 2*a2    )*HPHP + pos] = q0;
            g_q[(b*AA + 2*a2 + 1)*HPHP + pos] = q1;
        }
        vmax = fmaxf(fmaxf(q0, q1), vmax);
    }
    g_vbuf[iter & 1][tid] = vmax;
}

// ---------------- head -------------------------------------------------------
__global__ void head_k(const float* __restrict__ a1w, const float* __restrict__ a1b,
                       const float* __restrict__ a2w, const float* __restrict__ a2b,
                       float* __restrict__ out) {
    __shared__ float a1s[HIDC*AA];
    __shared__ float a2s[AA*HIDC];
    __shared__ float b1s[HIDC];
    __shared__ float b2s[AA];
    int t = threadIdx.x;
    for (int i = t; i < HIDC*AA; i += blockDim.x) { a1s[i] = a1w[i]; a2s[i] = a2w[i]; }
    for (int i = t; i < HIDC; i += blockDim.x) b1s[i] = a1b[i];
    if (t < AA) b2s[t] = a2b[t];
    __syncthreads();
    int tid = blockIdx.x * blockDim.x + t;
    if (tid >= BB*GG) return;
    int b = tid / GG, pos = tid % GG, y = pos / G, x = pos % G;
    float qv[AA];
    #pragma unroll
    for (int a = 0; a < AA; a++) qv[a] = g_q[(b*AA + a)*HPHP + y*HP + x];
    float lg[AA];
    #pragma unroll
    for (int a = 0; a < AA; a++) lg[a] = 0.f;
    for (int c = 0; c < HIDC; c++) {
        float m = b1s[c];
        #pragma unroll
        for (int a = 0; a < AA; a++) m += qv[a] * a1s[c*AA + a];
        m = fmaxf(m, 0.f);
        #pragma unroll
        for (int a = 0; a < AA; a++) lg[a] += m * a2s[a*HIDC + c];
    }
    #pragma unroll
    for (int a = 0; a < AA; a++) out[(b*AA + a)*GG + pos] = lg[a] + b2s[a];
}

// ---------------- launch -----------------------------------------------------
extern "C" void kernel_launch(void* const* d_in, const int* in_sizes, int n_in,
                              void* d_out, int out_size) {
    const float* grid = (const float*)d_in[0];
    const float* h1w = (const float*)d_in[3];
    const float* h1b = (const float*)d_in[4];
    const float* h2w = (const float*)d_in[5];
    const float* h2b = (const float*)d_in[6];
    const float* rw  = (const float*)d_in[7];
    const float* tw  = (const float*)d_in[8];
    const float* a1w = (const float*)d_in[9];
    const float* a1b = (const float*)d_in[10];
    const float* a2w = (const float*)d_in[11];
    const float* a2b = (const float*)d_in[12];
    float* out = (float*)d_out;

    // smem bytes: (2*A + 2*B)*4 + bias
    const int SMEM2  = (2*128*20 + 2*160*20) * 4 + HIDC*4 + 64;  // ~47.3 KB
    const int SMEMRT = (2*128*20 + 2*80*20) * 4 + 64;            // ~33.3 KB
    cudaFuncSetAttribute(mma_conv_k<10, G, 1, GG, 0, 2>,
                         cudaFuncAttributeMaxDynamicSharedMemorySize, SMEM2);
    cudaFuncSetAttribute(mma_conv_k<5, HP, 2, HPHP, 1, 3>,
                         cudaFuncAttributeMaxDynamicSharedMemorySize, SMEMRT);

    prep_k<<<(45*160*32 + 255)/256, 256>>>(h2w, rw, tw);
    conv1T_k<<<dim3((GG + 31)/32, BB), 256>>>(grid, h1w, h1b);
    mma_conv_k<10, G, 1, GG, 0, 2><<<dim3((GG + 127)/128, BB), 256, SMEM2>>>(h2b);
    mma_conv_k<5, HP, 2, HPHP, 1, 3><<<dim3((HPHP + 127)/128, BB), 256, SMEMRT>>>(nullptr);
    softmax_k<<<(BB*4*HPHP + 255)/256, 256>>>();
    for (int it = 0; it < KIT; it++)
        vi_step_k<<<(BB*HPHP + 255)/256, 256>>>(it, it == KIT - 1 ? 1 : 0);
    head_k<<<(BB*GG + 255)/256, 256>>>(a1w, a1b, a2w, a2b, out);
}

// round 12
// speedup vs baseline: 2.4854x; 1.0142x over previous
#include <cuda_runtime.h>
#include <cuda_fp16.h>
#include <cstdint>

// Problem constants
#define BB   128
#define CIN  2
#define HIDC 150
#define AA   8
#define KIT  30
#define G    49
#define HP   51
#define GG   (G*G)      // 2401
#define HPHP (HP*HP)    // 2601
#define CPAD 160        // padded channel-last stride (halfs)
#define NCH  46         // chunk count padded to even (last = zero chunk)

// ---------------- scratch (device globals; 16B-aligned) ----------------------
__device__ __align__(16) __half g_hT [BB*GG*CPAD];   // conv1 out, channel-last fp16
__device__ __align__(16) __half g_h2T[BB*GG*CPAD];   // conv2 out, channel-last fp16
__device__ __align__(16) float g_tr  [BB*AA*9*HPHP]; // trans (fp32, pre-softmax)
__device__ __align__(16) uint32_t g_tru[BB*9*4*HPHP];// softmaxed trans, u16 pairs
__device__ __align__(16) float g_rew [BB*HPHP];
__device__ __align__(16) float g_vbuf[2][BB*HPHP];
__device__ __align__(16) float g_q   [BB*AA*HPHP];
__device__ __align__(16) __half g_wB2 [NCH*160*32];  // conv2 B [s][n][k32] fp16
__device__ __align__(16) __half g_wBrt[NCH*80*32];   // convrt B [s][n][k32] fp16

// ============================ PTX helpers ====================================
__device__ __forceinline__ uint32_t smem_u32(const void* p) {
    uint32_t a;
    asm("{ .reg .u64 t; cvta.to.shared.u64 t, %1; cvt.u32.u64 %0, t; }" : "=r"(a) : "l"(p));
    return a;
}
__device__ __forceinline__ void cpa16(uint32_t dst, const void* src, uint32_t sz) {
    asm volatile("cp.async.cg.shared.global [%0], [%1], 16, %2;"
                 :: "r"(dst), "l"(src), "r"(sz) : "memory");
}
#define CP_COMMIT() asm volatile("cp.async.commit_group;" ::: "memory")
#define CP_WAIT1()  asm volatile("cp.async.wait_group 1;" ::: "memory")
#define CP_WAIT0()  asm volatile("cp.async.wait_group 0;" ::: "memory")
__device__ __forceinline__ void mma16(float* c, const uint32_t* a, const uint32_t* b) {
    asm volatile("mma.sync.aligned.m16n8k16.row.col.f32.f16.f16.f32 "
        "{%0,%1,%2,%3}, {%4,%5,%6,%7}, {%8,%9}, {%0,%1,%2,%3};"
        : "+f"(c[0]), "+f"(c[1]), "+f"(c[2]), "+f"(c[3])
        : "r"(a[0]), "r"(a[1]), "r"(a[2]), "r"(a[3]), "r"(b[0]), "r"(b[1]));
}

// ---------------- weight prep: fp16 B tiles [s][n][k(32)], s<45 real ---------
__global__ void prep_k(const float* __restrict__ h2w,
                       const float* __restrict__ rw,
                       const float* __restrict__ tw) {
    int i = blockIdx.x * blockDim.x + threadIdx.x;
    if (i < NCH*160*32) {
        int k = i & 31, n = (i >> 5) % 160, s = i / (160*32);
        float v = 0.f;
        if (s < 45) {
            int tap = s/5, ci = (s%5)*32 + k;
            if (n < HIDC && ci < HIDC) v = h2w[(n*HIDC + ci)*9 + tap];
        }
        g_wB2[i] = __float2half_rn(v);
    }
    if (i < NCH*80*32) {
        int k = i & 31, n = (i >> 5) % 80, s = i / (80*32);
        float v = 0.f;
        if (s < 45) {
            int tap = s/5, ci = (s%5)*32 + k;
            if (ci < HIDC) {
                if (n == 0)      v = rw[ci*9 + tap];
                else if (n < 73) v = tw[((n-1)*HIDC + ci)*9 + tap];
            }
        }
        g_wBrt[i] = __float2half_rn(v);
    }
}

// -------- conv1 fused with channel-last transpose: grid -> g_hT (fp16) -------
__global__ void conv1T_k(const float* __restrict__ gin,
                         const float* __restrict__ w,
                         const float* __restrict__ bias) {
    __shared__ float ws[HIDC*CIN*9];
    __shared__ float bs[HIDC];
    __shared__ __align__(16) __half tile[32*176];
    int t = threadIdx.x;
    for (int i = t; i < HIDC*CIN*9; i += 256) ws[i] = w[i];
    for (int i = t; i < HIDC; i += 256) bs[i] = bias[i];
    __syncthreads();
    int pos0 = blockIdx.x * 32, b = blockIdx.y;
    int posi = t & 31, colane = t >> 5;
    int pos = pos0 + posi;
    bool okp = pos < GG;
    int y = okp ? pos / G : 0, x = okp ? pos % G : 0;
    float gv[CIN][9];
    #pragma unroll
    for (int ci = 0; ci < CIN; ci++)
        #pragma unroll
        for (int k = 0; k < 9; k++) {
            int r = y + k/3 - 1, c = x + k%3 - 1;
            gv[ci][k] = (okp && r >= 0 && r < G && c >= 0 && c < G)
                        ? gin[(b*CIN + ci)*GG + r*G + c] : 0.f;
        }
    #pragma unroll
    for (int j = 0; j < 20; j++) {
        int co = colane + 8*j;
        float out = 0.f;
        if (co < HIDC) {
            float acc = bs[co];
            #pragma unroll
            for (int ci = 0; ci < CIN; ci++)
                #pragma unroll
                for (int k = 0; k < 9; k++)
                    acc += gv[ci][k] * ws[(co*CIN + ci)*9 + k];
            out = fmaxf(acc, 0.f);
        }
        tile[posi*176 + co] = __float2half_rn(out);
    }
    __syncthreads();
    #pragma unroll
    for (int j = 0; j < 3; j++) {
        int qi = t + 256*j;
        if (qi < 640) {
            int row = qi / 20, q = qi - row*20;
            if (pos0 + row < GG) {
                *(uint4*)&g_hT[((size_t)(b*GG + pos0 + row))*CPAD + q*8] =
                    *(const uint4*)&tile[row*176 + q*8];
            }
        }
    }
}

// ========= fp16 mma.sync m16n8k16 implicit-GEMM conv, PAIRED chunks ==========
// Slot = 2 consecutive K=32 chunks (one commit group). 23 pairs, 46 barriers.
// MODE 0: conv2 (g_hT -> relu+bias -> g_h2T fp16), NFRAG=10 (N=160)
// MODE 1: convrt (g_h2T -> g_rew / g_tr fp32), NFRAG=5 (N=80)
template<int NFRAG, int OW, int PADC, int PTOT, int MODE, int MINB>
__global__ void __launch_bounds__(256, MINB) mma_conv_k(const float* __restrict__ bias) {
    constexpr int NOUT_PAD = NFRAG * 16;
    constexpr int RSTR = 20;                        // b32 per row
    constexpr int AW = 128 * RSTR;                  // b32 per A chunk (2560)
    constexpr int BW = NOUT_PAD * RSTR;             // b32 per B chunk
    constexpr int ASLOT = 2*AW, BSLOT = 2*BW;       // slot = chunk pair
    constexpr int BQN = NOUT_PAD * 4;               // quads per B chunk
    extern __shared__ __align__(16) uint32_t smu[];
    float* biasS = (float*)(smu + 2*ASLOT + 2*BSLOT);
    const __half* inH = (MODE == 0) ? g_hT : g_h2T;
    const __half* wB  = (MODE == 0) ? g_wB2 : g_wBrt;

    int t = threadIdx.x;
    int b = blockIdx.y, tile0 = blockIdx.x * 128;
    uint32_t smb = smem_u32(smu);

    if (MODE == 0) for (int i = t; i < HIDC; i += 256) biasS[i] = bias[i];

    // A-load invariants: thread covers rows (t>>2) and (t>>2)+64, quad t&3
    const int aq = t & 3;
    int yy[2], xx[2];
    uint32_t dA[2];
    #pragma unroll
    for (int i = 0; i < 2; i++) {
        int row = (t >> 2) + 64*i;
        int pos = tile0 + row;
        yy[i] = pos / OW;
        xx[i] = pos - yy[i]*OW;
        dA[i] = (uint32_t)(row*RSTR*4 + aq*16);
    }
    const __half* inB = inH + (size_t)b*GG*CPAD + aq*8;

    // load one pair of chunks (2p, 2p+1) into slot; single commit
    auto load_pair = [&](int p, int slot) {
        #pragma unroll
        for (int j = 0; j < 2; j++) {
            int s = 2*p + j;
            int tap = s / 5, cc = s - tap*5;
            int dyp = tap/3 - PADC, dxp = tap%3 - PADC, ci0 = cc*32;
            bool real = (s < 45);
            uint32_t Ab = smb + (uint32_t)(slot*ASLOT + j*AW)*4;
            #pragma unroll
            for (int i = 0; i < 2; i++) {
                int ir = yy[i] + dyp, ic = xx[i] + dxp;
                bool ok = real && ((unsigned)ir < G) && ((unsigned)ic < G);
                const __half* src = inB + (size_t)(ok ? (ir*G + ic) : 0)*CPAD + ci0;
                cpa16(Ab + dA[i], src, ok ? 16u : 0u);
            }
            uint32_t Bb = smb + (uint32_t)(2*ASLOT + slot*BSLOT + j*BW)*4;
            const __half* wsrc = wB + (size_t)s*NOUT_PAD*32;
            #pragma unroll
            for (int jj = 0; jj < (BQN + 255)/256; jj++) {
                int qi = t + 256*jj;
                if (qi < BQN) {
                    int n = qi >> 2, q = qi & 3;
                    cpa16(Bb + (uint32_t)(n*RSTR*4 + q*16), wsrc + n*32 + q*8, 16u);
                }
            }
        }
        CP_COMMIT();
    };

    const int lane = t & 31, wid = t >> 5;
    const int gid = lane >> 2, tig = lane & 3;
    const int m0w = (wid >> 1) * 32, n0w = (wid & 1) * NFRAG * 8;

    float c[2][NFRAG][4];
    #pragma unroll
    for (int mf = 0; mf < 2; mf++)
        #pragma unroll
        for (int nf = 0; nf < NFRAG; nf++)
            #pragma unroll
            for (int e = 0; e < 4; e++) c[mf][nf][e] = 0.f;

    constexpr int NP = NCH/2;     // 23 pairs
    load_pair(0, 0);
    for (int p = 0; p < NP; p++) {
        int cur = p & 1;
        if (p < NP-1) { load_pair(p + 1, cur ^ 1); CP_WAIT1(); }
        else          { CP_WAIT0(); }
        __syncthreads();
        #pragma unroll
        for (int j = 0; j < 2; j++) {
            const uint32_t* As = smu + cur*ASLOT + j*AW;
            const uint32_t* Bs = smu + 2*ASLOT + cur*BSLOT + j*BW;
            #pragma unroll
            for (int ks = 0; ks < 2; ks++) {
                int koff = ks*8 + tig;
                uint32_t a[2][4];
                #pragma unroll
                for (int mf = 0; mf < 2; mf++) {
                    int r = m0w + mf*16 + gid;
                    a[mf][0] = As[r*RSTR + koff];
                    a[mf][1] = As[(r+8)*RSTR + koff];
                    a[mf][2] = As[r*RSTR + koff + 4];
                    a[mf][3] = As[(r+8)*RSTR + koff + 4];
                }
                #pragma unroll
                for (int nf = 0; nf < NFRAG; nf++) {
                    int nc = n0w + nf*8 + gid;
                    uint32_t bv[2];
                    bv[0] = Bs[nc*RSTR + koff];
                    bv[1] = Bs[nc*RSTR + koff + 4];
                    mma16(c[0][nf], a[0], bv);
                    mma16(c[1][nf], a[1], bv);
                }
            }
        }
        __syncthreads();
    }

    // ---- epilogue ----
    #pragma unroll
    for (int mf = 0; mf < 2; mf++) {
        #pragma unroll
        for (int rr = 0; rr < 2; rr++) {
            int pos = tile0 + m0w + mf*16 + gid + rr*8;
            if (pos >= PTOT) continue;
            if (MODE == 0) {
                __half* op = &g_h2T[((size_t)(b*GG + pos))*CPAD];
                #pragma unroll
                for (int nf = 0; nf < NFRAG; nf++) {
                    int co = n0w + nf*8 + 2*tig;
                    float v0 = c[mf][nf][rr*2 + 0], v1 = c[mf][nf][rr*2 + 1];
                    float o0 = (co   < HIDC) ? fmaxf(v0 + biasS[co],   0.f) : 0.f;
                    float o1 = (co+1 < HIDC) ? fmaxf(v1 + biasS[co+1], 0.f) : 0.f;
                    *(__half2*)&op[co] = __floats2half2_rn(o0, o1);
                }
            } else {
                #pragma unroll
                for (int nf = 0; nf < NFRAG; nf++) {
                    int co = n0w + nf*8 + 2*tig;
                    float v0 = c[mf][nf][rr*2 + 0], v1 = c[mf][nf][rr*2 + 1];
                    if (co == 0)      g_rew[b*HPHP + pos] = v0;
                    else if (co < 73) g_tr[((size_t)(b*72 + co - 1))*HPHP + pos] = v0;
                    if (co + 1 < 73)  g_tr[((size_t)(b*72 + co))*HPHP + pos] = v1;
                }
            }
        }
    }
}

// ------------- softmax over 9 taps -> u16 pairs (a, a+1) ---------------------
__global__ void softmax_k() {
    int tid = blockIdx.x * blockDim.x + threadIdx.x;
    if (tid >= BB*4*HPHP) return;
    int pos = tid % HPHP;
    int t2  = tid / HPHP;
    int a2 = t2 & 3, b = t2 >> 2;
    size_t base0 = ((size_t)(b*8 + 2*a2))*9*HPHP + pos;
    float v0[9], v1[9];
    float m0 = -1e30f, m1 = -1e30f;
    #pragma unroll
    for (int k = 0; k < 9; k++) {
        v0[k] = g_tr[base0 + (size_t)k*HPHP];           m0 = fmaxf(m0, v0[k]);
        v1[k] = g_tr[base0 + (size_t)(9 + k)*HPHP];     m1 = fmaxf(m1, v1[k]);
    }
    float s0 = 0.f, s1 = 0.f;
    #pragma unroll
    for (int k = 0; k < 9; k++) {
        v0[k] = expf(v0[k] - m0); s0 += v0[k];
        v1[k] = expf(v1[k] - m1); s1 += v1[k];
    }
    float i0 = 65536.f / s0, i1 = 65536.f / s1;
    #pragma unroll
    for (int k = 0; k < 9; k++) {
        float y0 = fmaf(v0[k], i0, 8388608.f);
        float y1 = fmaf(v1[k], i1, 8388608.f);
        uint32_t pk = __byte_perm(__float_as_uint(y0), __float_as_uint(y1), 0x5410);
        g_tru[((size_t)(b*9 + k)*4 + a2)*HPHP + pos] = pk;
    }
}

// ---------------- one value-iteration step (u16 trans) -----------------------
__global__ void vi_step_k(int iter, int store_q) {
    int tid = blockIdx.x * blockDim.x + threadIdx.x;
    if (tid >= BB*HPHP) return;
    int b = tid / HPHP, pos = tid - b*HPHP, y = pos / HP, x = pos - y*HP;
    const float* vin = g_vbuf[(iter & 1) ^ 1];
    float p[9];
    if (iter == 0) {
        #pragma unroll
        for (int k = 0; k < 9; k++) p[k] = 0.f;
    } else {
        #pragma unroll
        for (int k = 0; k < 9; k++) {
            int r = y + k/3 - 1, c = x + k%3 - 1;
            p[k] = (r >= 0 && r < HP && c >= 0 && c < HP)
                   ? vin[b*HPHP + r*HP + c] : 0.f;
        }
    }
    float r0 = g_rew[tid];
    float vmax = -1e30f;
    const uint32_t* trb = g_tru + (size_t)b*36*HPHP + pos;
    #pragma unroll
    for (int a2 = 0; a2 < 4; a2++) {
        float q0 = r0, q1 = r0;
        #pragma unroll
        for (int k = 0; k < 9; k++) {
            uint32_t w = trb[(size_t)(k*4 + a2)*HPHP];
            float f0 = __uint_as_float(__byte_perm(w, 0x4B000000u, 0x7410));
            float f1 = __uint_as_float(__byte_perm(w, 0x4B000000u, 0x7432));
            float P0 = fmaf(f0, 1.f/65536.f, -128.f);
            float P1 = fmaf(f1, 1.f/65536.f, -128.f);
            q0 = fmaf(P0, p[k], q0);
            q1 = fmaf(P1, p[k], q1);
        }
        if (store_q) {
            g_q[(b*AA + 2*a2    )*HPHP + pos] = q0;
            g_q[(b*AA + 2*a2 + 1)*HPHP + pos] = q1;
        }
        vmax = fmaxf(fmaxf(q0, q1), vmax);
    }
    g_vbuf[iter & 1][tid] = vmax;
}

// ---------------- head -------------------------------------------------------
__global__ void head_k(const float* __restrict__ a1w, const float* __restrict__ a1b,
                       const float* __restrict__ a2w, const float* __restrict__ a2b,
                       float* __restrict__ out) {
    __shared__ float a1s[HIDC*AA];
    __shared__ float a2s[AA*HIDC];
    __shared__ float b1s[HIDC];
    __shared__ float b2s[AA];
    int t = threadIdx.x;
    for (int i = t; i < HIDC*AA; i += blockDim.x) { a1s[i] = a1w[i]; a2s[i] = a2w[i]; }
    for (int i = t; i < HIDC; i += blockDim.x) b1s[i] = a1b[i];
    if (t < AA) b2s[t] = a2b[t];
    __syncthreads();
    int tid = blockIdx.x * blockDim.x + t;
    if (tid >= BB*GG) return;
    int b = tid / GG, pos = tid % GG, y = pos / G, x = pos % G;
    float qv[AA];
    #pragma unroll
    for (int a = 0; a < AA; a++) qv[a] = g_q[(b*AA + a)*HPHP + y*HP + x];
    float lg[AA];
    #pragma unroll
    for (int a = 0; a < AA; a++) lg[a] = 0.f;
    for (int c = 0; c < HIDC; c++) {
        float m = b1s[c];
        #pragma unroll
        for (int a = 0; a < AA; a++) m += qv[a] * a1s[c*AA + a];
        m = fmaxf(m, 0.f);
        #pragma unroll
        for (int a = 0; a < AA; a++) lg[a] += m * a2s[a*HIDC + c];
    }
    #pragma unroll
    for (int a = 0; a < AA; a++) out[(b*AA + a)*GG + pos] = lg[a] + b2s[a];
}

// ---------------- launch -----------------------------------------------------
extern "C" void kernel_launch(void* const* d_in, const int* in_sizes, int n_in,
                              void* d_out, int out_size) {
    const float* grid = (const float*)d_in[0];
    const float* h1w = (const float*)d_in[3];
    const float* h1b = (const float*)d_in[4];
    const float* h2w = (const float*)d_in[5];
    const float* h2b = (const float*)d_in[6];
    const float* rw  = (const float*)d_in[7];
    const float* tw  = (const float*)d_in[8];
    const float* a1w = (const float*)d_in[9];
    const float* a1b = (const float*)d_in[10];
    const float* a2w = (const float*)d_in[11];
    const float* a2b = (const float*)d_in[12];
    float* out = (float*)d_out;

    // smem bytes: (2*ASLOT + 2*BSLOT)*4 + bias
    const int SMEM2  = (4*128*20 + 4*160*20) * 4 + HIDC*4 + 64;  // ~94.4 KB
    const int SMEMRT = (4*128*20 + 4*80*20) * 4 + 64;            // ~66.6 KB
    cudaFuncSetAttribute(mma_conv_k<10, G, 1, GG, 0, 2>,
                         cudaFuncAttributeMaxDynamicSharedMemorySize, SMEM2);
    cudaFuncSetAttribute(mma_conv_k<5, HP, 2, HPHP, 1, 3>,
                         cudaFuncAttributeMaxDynamicSharedMemorySize, SMEMRT);

    prep_k<<<(NCH*160*32 + 255)/256, 256>>>(h2w, rw, tw);
    conv1T_k<<<dim3((GG + 31)/32, BB), 256>>>(grid, h1w, h1b);
    mma_conv_k<10, G, 1, GG, 0, 2><<<dim3((GG + 127)/128, BB), 256, SMEM2>>>(h2b);
    mma_conv_k<5, HP, 2, HPHP, 1, 3><<<dim3((HPHP + 127)/128, BB), 256, SMEMRT>>>(nullptr);
    softmax_k<<<(BB*4*HPHP + 255)/256, 256>>>();
    for (int it = 0; it < KIT; it++)
        vi_step_k<<<(BB*HPHP + 255)/256, 256>>>(it, it == KIT - 1 ? 1 : 0);
    head_k<<<(BB*GG + 255)/256, 256>>>(a1w, a1b, a2w, a2b, out);
}

// round 13
// speedup vs baseline: 2.6542x; 1.0679x over previous
#include <cuda_runtime.h>
#include <cuda_fp16.h>
#include <cstdint>

// Problem constants
#define BB   128
#define CIN  2
#define HIDC 150
#define AA   8
#define KIT  30
#define G    49
#define HP   51
#define GG   (G*G)      // 2401
#define HPHP (HP*HP)    // 2601
#define CPAD 160        // padded channel-last stride (halfs)
#define NCH  46         // chunk count padded to even (last = zero chunk)

// ---------------- scratch (device globals; 16B-aligned) ----------------------
__device__ __align__(16) __half g_hT [BB*GG*CPAD];   // conv1 out, channel-last fp16
__device__ __align__(16) __half g_h2T[BB*GG*CPAD];   // conv2 out, channel-last fp16
__device__ __align__(16) float g_tr  [BB*AA*9*HPHP]; // trans (fp32, pre-softmax)
__device__ __align__(16) uint32_t g_tru[BB*9*4*HPHP];// softmaxed trans, u16 pairs
__device__ __align__(16) float g_rew [BB*HPHP];
__device__ __align__(16) float g_vbuf[2][BB*HPHP];
__device__ __align__(16) float g_q   [BB*AA*HPHP];
__device__ __align__(16) __half g_wB2 [NCH*160*32];  // conv2 B [s][n][k32] fp16
__device__ __align__(16) __half g_wBrt[NCH*80*32];   // convrt B [s][n][k32] fp16

// ============================ PTX helpers ====================================
__device__ __forceinline__ uint32_t smem_u32(const void* p) {
    uint32_t a;
    asm("{ .reg .u64 t; cvta.to.shared.u64 t, %1; cvt.u32.u64 %0, t; }" : "=r"(a) : "l"(p));
    return a;
}
__device__ __forceinline__ void cpa16(uint32_t dst, const void* src, uint32_t sz) {
    asm volatile("cp.async.cg.shared.global [%0], [%1], 16, %2;"
                 :: "r"(dst), "l"(src), "r"(sz) : "memory");
}
#define CP_COMMIT() asm volatile("cp.async.commit_group;" ::: "memory")
#define CP_WAIT1()  asm volatile("cp.async.wait_group 1;" ::: "memory")
#define CP_WAIT0()  asm volatile("cp.async.wait_group 0;" ::: "memory")
__device__ __forceinline__ void mma16(float* c, const uint32_t* a, const uint32_t* b) {
    asm volatile("mma.sync.aligned.m16n8k16.row.col.f32.f16.f16.f32 "
        "{%0,%1,%2,%3}, {%4,%5,%6,%7}, {%8,%9}, {%0,%1,%2,%3};"
        : "+f"(c[0]), "+f"(c[1]), "+f"(c[2]), "+f"(c[3])
        : "r"(a[0]), "r"(a[1]), "r"(a[2]), "r"(a[3]), "r"(b[0]), "r"(b[1]));
}
__device__ __forceinline__ void ldsm_x4(uint32_t* r, uint32_t addr) {
    asm volatile("ldmatrix.sync.aligned.m8n8.x4.shared.b16 {%0,%1,%2,%3}, [%4];"
        : "=r"(r[0]), "=r"(r[1]), "=r"(r[2]), "=r"(r[3]) : "r"(addr));
}
__device__ __forceinline__ void ldsm_x2(uint32_t* r, uint32_t addr) {
    asm volatile("ldmatrix.sync.aligned.m8n8.x2.shared.b16 {%0,%1}, [%2];"
        : "=r"(r[0]), "=r"(r[1]) : "r"(addr));
}

// ---------------- weight prep: fp16 B tiles [s][n][k(32)], s<45 real ---------
__global__ void prep_k(const float* __restrict__ h2w,
                       const float* __restrict__ rw,
                       const float* __restrict__ tw) {
    int i = blockIdx.x * blockDim.x + threadIdx.x;
    if (i < NCH*160*32) {
        int k = i & 31, n = (i >> 5) % 160, s = i / (160*32);
        float v = 0.f;
        if (s < 45) {
            int tap = s/5, ci = (s%5)*32 + k;
            if (n < HIDC && ci < HIDC) v = h2w[(n*HIDC + ci)*9 + tap];
        }
        g_wB2[i] = __float2half_rn(v);
    }
    if (i < NCH*80*32) {
        int k = i & 31, n = (i >> 5) % 80, s = i / (80*32);
        float v = 0.f;
        if (s < 45) {
            int tap = s/5, ci = (s%5)*32 + k;
            if (ci < HIDC) {
                if (n == 0)      v = rw[ci*9 + tap];
                else if (n < 73) v = tw[((n-1)*HIDC + ci)*9 + tap];
            }
        }
        g_wBrt[i] = __float2half_rn(v);
    }
}

// -------- conv1 fused with channel-last transpose: grid -> g_hT (fp16) -------
__global__ void conv1T_k(const float* __restrict__ gin,
                         const float* __restrict__ w,
                         const float* __restrict__ bias) {
    __shared__ float ws[HIDC*CIN*9];
    __shared__ float bs[HIDC];
    __shared__ __align__(16) __half tile[32*176];
    int t = threadIdx.x;
    for (int i = t; i < HIDC*CIN*9; i += 256) ws[i] = w[i];
    for (int i = t; i < HIDC; i += 256) bs[i] = bias[i];
    __syncthreads();
    int pos0 = blockIdx.x * 32, b = blockIdx.y;
    int posi = t & 31, colane = t >> 5;
    int pos = pos0 + posi;
    bool okp = pos < GG;
    int y = okp ? pos / G : 0, x = okp ? pos % G : 0;
    float gv[CIN][9];
    #pragma unroll
    for (int ci = 0; ci < CIN; ci++)
        #pragma unroll
        for (int k = 0; k < 9; k++) {
            int r = y + k/3 - 1, c = x + k%3 - 1;
            gv[ci][k] = (okp && r >= 0 && r < G && c >= 0 && c < G)
                        ? gin[(b*CIN + ci)*GG + r*G + c] : 0.f;
        }
    #pragma unroll
    for (int j = 0; j < 20; j++) {
        int co = colane + 8*j;
        float out = 0.f;
        if (co < HIDC) {
            float acc = bs[co];
            #pragma unroll
            for (int ci = 0; ci < CIN; ci++)
                #pragma unroll
                for (int k = 0; k < 9; k++)
                    acc += gv[ci][k] * ws[(co*CIN + ci)*9 + k];
            out = fmaxf(acc, 0.f);
        }
        tile[posi*176 + co] = __float2half_rn(out);
    }
    __syncthreads();
    #pragma unroll
    for (int j = 0; j < 3; j++) {
        int qi = t + 256*j;
        if (qi < 640) {
            int row = qi / 20, q = qi - row*20;
            if (pos0 + row < GG) {
                *(uint4*)&g_hT[((size_t)(b*GG + pos0 + row))*CPAD + q*8] =
                    *(const uint4*)&tile[row*176 + q*8];
            }
        }
    }
}

// ========= fp16 mma.sync m16n8k16 implicit-GEMM conv, ldmatrix fragments =====
// Slot = 2 consecutive K=32 chunks. Fragments via LDSM (x4/x2).
// MODE 0: conv2 (g_hT -> relu+bias -> g_h2T fp16), NFRAG=10 (N=160)
// MODE 1: convrt (g_h2T -> g_rew / g_tr fp32), NFRAG=5 (N=80)
template<int NFRAG, int OW, int PADC, int PTOT, int MODE, int MINB>
__global__ void __launch_bounds__(256, MINB) mma_conv_k(const float* __restrict__ bias) {
    constexpr int NOUT_PAD = NFRAG * 16;
    constexpr int RSTR = 20;                        // b32 per row
    constexpr int AW = 128 * RSTR;                  // b32 per A chunk (2560)
    constexpr int BW = NOUT_PAD * RSTR;             // b32 per B chunk
    constexpr int ASLOT = 2*AW, BSLOT = 2*BW;       // slot = chunk pair
    constexpr int BQN = NOUT_PAD * 4;               // quads per B chunk
    constexpr int NPAIR = NFRAG/2;
    constexpr bool ODD = (NFRAG & 1) != 0;
    extern __shared__ __align__(16) uint32_t smu[];
    float* biasS = (float*)(smu + 2*ASLOT + 2*BSLOT);
    const __half* inH = (MODE == 0) ? g_hT : g_h2T;
    const __half* wB  = (MODE == 0) ? g_wB2 : g_wBrt;

    int t = threadIdx.x;
    int b = blockIdx.y, tile0 = blockIdx.x * 128;
    uint32_t smb = smem_u32(smu);

    if (MODE == 0) for (int i = t; i < HIDC; i += 256) biasS[i] = bias[i];

    // A-load invariants: thread covers rows (t>>2) and (t>>2)+64, quad t&3
    const int aq = t & 3;
    int yy[2], xx[2];
    uint32_t dA[2];
    #pragma unroll
    for (int i = 0; i < 2; i++) {
        int row = (t >> 2) + 64*i;
        int pos = tile0 + row;
        yy[i] = pos / OW;
        xx[i] = pos - yy[i]*OW;
        dA[i] = (uint32_t)(row*RSTR*4 + aq*16);
    }
    const __half* inB = inH + (size_t)b*GG*CPAD + aq*8;

    // load one pair of chunks (2p, 2p+1) into slot; single commit
    auto load_pair = [&](int p, int slot) {
        #pragma unroll
        for (int j = 0; j < 2; j++) {
            int s = 2*p + j;
            int tap = s / 5, cc = s - tap*5;
            int dyp = tap/3 - PADC, dxp = tap%3 - PADC, ci0 = cc*32;
            bool real = (s < 45);
            uint32_t Ab = smb + (uint32_t)(slot*ASLOT + j*AW)*4;
            #pragma unroll
            for (int i = 0; i < 2; i++) {
                int ir = yy[i] + dyp, ic = xx[i] + dxp;
                bool ok = real && ((unsigned)ir < G) && ((unsigned)ic < G);
                const __half* src = inB + (size_t)(ok ? (ir*G + ic) : 0)*CPAD + ci0;
                cpa16(Ab + dA[i], src, ok ? 16u : 0u);
            }
            uint32_t Bb = smb + (uint32_t)(2*ASLOT + slot*BSLOT + j*BW)*4;
            const __half* wsrc = wB + (size_t)s*NOUT_PAD*32;
            #pragma unroll
            for (int jj = 0; jj < (BQN + 255)/256; jj++) {
                int qi = t + 256*jj;
                if (qi < BQN) {
                    int n = qi >> 2, q = qi & 3;
                    cpa16(Bb + (uint32_t)(n*RSTR*4 + q*16), wsrc + n*32 + q*8, 16u);
                }
            }
        }
        CP_COMMIT();
    };

    const int lane = t & 31, wid = t >> 5;
    const int gid = lane >> 2, tig = lane & 3;
    const int m0w = (wid >> 1) * 32, n0w = (wid & 1) * NFRAG * 8;

    // ldmatrix per-thread byte offsets (invariant; add buffer base at use)
    // A x4: lanes 0-15 -> rows 0-15 (k 0-7), lanes 16-31 -> rows 0-15 (k 8-15)
    uint32_t aoff[2][2];
    #pragma unroll
    for (int mf = 0; mf < 2; mf++)
        #pragma unroll
        for (int ks = 0; ks < 2; ks++)
            aoff[mf][ks] = (uint32_t)(((m0w + mf*16 + (lane & 15))*RSTR
                                       + ks*8 + (lane >> 4)*4) * 4);
    // B x4 (n-pair): lanes {0-7,8-15,16-23,24-31} -> (n0-7,k0-7),(n0-7,k8-15),
    //                (n8-15,k0-7),(n8-15,k8-15)
    uint32_t boff[(NPAIR > 0 ? NPAIR : 1)][2];
    #pragma unroll
    for (int pr = 0; pr < NPAIR; pr++)
        #pragma unroll
        for (int ks = 0; ks < 2; ks++)
            boff[pr][ks] = (uint32_t)(((n0w + pr*16 + ((lane >> 4) << 3) + (lane & 7))*RSTR
                                       + ks*8 + (((lane >> 3) & 1) << 2)) * 4);
    uint32_t boff2[2];
    #pragma unroll
    for (int ks = 0; ks < 2; ks++)
        boff2[ks] = (uint32_t)(((n0w + (NFRAG-1)*8 + (lane & 7))*RSTR
                                + ks*8 + ((((lane & 15) >> 3) & 1) << 2)) * 4);

    float c[2][NFRAG][4];
    #pragma unroll
    for (int mf = 0; mf < 2; mf++)
        #pragma unroll
        for (int nf = 0; nf < NFRAG; nf++)
            #pragma unroll
            for (int e = 0; e < 4; e++) c[mf][nf][e] = 0.f;

    constexpr int NP = NCH/2;     // 23 pairs
    load_pair(0, 0);
    for (int p = 0; p < NP; p++) {
        int cur = p & 1;
        if (p < NP-1) { load_pair(p + 1, cur ^ 1); CP_WAIT1(); }
        else          { CP_WAIT0(); }
        __syncthreads();
        #pragma unroll
        for (int j = 0; j < 2; j++) {
            uint32_t Abase = smb + (uint32_t)(cur*ASLOT + j*AW)*4;
            uint32_t Bbase = smb + (uint32_t)(2*ASLOT + cur*BSLOT + j*BW)*4;
            #pragma unroll
            for (int ks = 0; ks < 2; ks++) {
                uint32_t a[2][4];
                ldsm_x4(a[0], Abase + aoff[0][ks]);
                ldsm_x4(a[1], Abase + aoff[1][ks]);
                uint32_t bv[NFRAG][2];
                #pragma unroll
                for (int pr = 0; pr < NPAIR; pr++) {
                    uint32_t r4[4];
                    ldsm_x4(r4, Bbase + boff[pr][ks]);
                    bv[2*pr][0] = r4[0]; bv[2*pr][1] = r4[1];
                    bv[2*pr+1][0] = r4[2]; bv[2*pr+1][1] = r4[3];
                }
                if (ODD) ldsm_x2(bv[NFRAG-1], Bbase + boff2[ks]);
                #pragma unroll
                for (int nf = 0; nf < NFRAG; nf++) {
                    mma16(c[0][nf], a[0], bv[nf]);
                    mma16(c[1][nf], a[1], bv[nf]);
                }
            }
        }
        __syncthreads();
    }

    // ---- epilogue ----
    #pragma unroll
    for (int mf = 0; mf < 2; mf++) {
        #pragma unroll
        for (int rr = 0; rr < 2; rr++) {
            int pos = tile0 + m0w + mf*16 + gid + rr*8;
            if (pos >= PTOT) continue;
            if (MODE == 0) {
                __half* op = &g_h2T[((size_t)(b*GG + pos))*CPAD];
                #pragma unroll
                for (int nf = 0; nf < NFRAG; nf++) {
                    int co = n0w + nf*8 + 2*tig;
                    float v0 = c[mf][nf][rr*2 + 0], v1 = c[mf][nf][rr*2 + 1];
                    float o0 = (co   < HIDC) ? fmaxf(v0 + biasS[co],   0.f) : 0.f;
                    float o1 = (co+1 < HIDC) ? fmaxf(v1 + biasS[co+1], 0.f) : 0.f;
                    *(__half2*)&op[co] = __floats2half2_rn(o0, o1);
                }
            } else {
                #pragma unroll
                for (int nf = 0; nf < NFRAG; nf++) {
                    int co = n0w + nf*8 + 2*tig;
                    float v0 = c[mf][nf][rr*2 + 0], v1 = c[mf][nf][rr*2 + 1];
                    if (co == 0)      g_rew[b*HPHP + pos] = v0;
                    else if (co < 73) g_tr[((size_t)(b*72 + co - 1))*HPHP + pos] = v0;
                    if (co + 1 < 73)  g_tr[((size_t)(b*72 + co))*HPHP + pos] = v1;
                }
            }
        }
    }
}

// ------------- softmax over 9 taps -> u16 pairs (a, a+1) ---------------------
__global__ void softmax_k() {
    int tid = blockIdx.x * blockDim.x + threadIdx.x;
    if (tid >= BB*4*HPHP) return;
    int pos = tid % HPHP;
    int t2  = tid / HPHP;
    int a2 = t2 & 3, b = t2 >> 2;
    size_t base0 = ((size_t)(b*8 + 2*a2))*9*HPHP + pos;
    float v0[9], v1[9];
    float m0 = -1e30f, m1 = -1e30f;
    #pragma unroll
    for (int k = 0; k < 9; k++) {
        v0[k] = g_tr[base0 + (size_t)k*HPHP];           m0 = fmaxf(m0, v0[k]);
        v1[k] = g_tr[base0 + (size_t)(9 + k)*HPHP];     m1 = fmaxf(m1, v1[k]);
    }
    float s0 = 0.f, s1 = 0.f;
    #pragma unroll
    for (int k = 0; k < 9; k++) {
        v0[k] = expf(v0[k] - m0); s0 += v0[k];
        v1[k] = expf(v1[k] - m1); s1 += v1[k];
    }
    float i0 = 65536.f / s0, i1 = 65536.f / s1;
    #pragma unroll
    for (int k = 0; k < 9; k++) {
        float y0 = fmaf(v0[k], i0, 8388608.f);
        float y1 = fmaf(v1[k], i1, 8388608.f);
        uint32_t pk = __byte_perm(__float_as_uint(y0), __float_as_uint(y1), 0x5410);
        g_tru[((size_t)(b*9 + k)*4 + a2)*HPHP + pos] = pk;
    }
}

// ---------------- one value-iteration step (u16 trans) -----------------------
__global__ void vi_step_k(int iter, int store_q) {
    int tid = blockIdx.x * blockDim.x + threadIdx.x;
    if (tid >= BB*HPHP) return;
    int b = tid / HPHP, pos = tid - b*HPHP, y = pos / HP, x = pos - y*HP;
    const float* vin = g_vbuf[(iter & 1) ^ 1];
    float p[9];
    if (iter == 0) {
        #pragma unroll
        for (int k = 0; k < 9; k++) p[k] = 0.f;
    } else {
        #pragma unroll
        for (int k = 0; k < 9; k++) {
            int r = y + k/3 - 1, c = x + k%3 - 1;
            p[k] = (r >= 0 && r < HP && c >= 0 && c < HP)
                   ? vin[b*HPHP + r*HP + c] : 0.f;
        }
    }
    float r0 = g_rew[tid];
    float vmax = -1e30f;
    const uint32_t* trb = g_tru + (size_t)b*36*HPHP + pos;
    #pragma unroll
    for (int a2 = 0; a2 < 4; a2++) {
        float q0 = r0, q1 = r0;
        #pragma unroll
        for (int k = 0; k < 9; k++) {
            uint32_t w = trb[(size_t)(k*4 + a2)*HPHP];
            float f0 = __uint_as_float(__byte_perm(w, 0x4B000000u, 0x7410));
            float f1 = __uint_as_float(__byte_perm(w, 0x4B000000u, 0x7432));
            float P0 = fmaf(f0, 1.f/65536.f, -128.f);
            float P1 = fmaf(f1, 1.f/65536.f, -128.f);
            q0 = fmaf(P0, p[k], q0);
            q1 = fmaf(P1, p[k], q1);
        }
        if (store_q) {
            g_q[(b*AA + 2*a2    )*HPHP + pos] = q0;
            g_q[(b*AA + 2*a2 + 1)*HPHP + pos] = q1;
        }
        vmax = fmaxf(fmaxf(q0, q1), vmax);
    }
    g_vbuf[iter & 1][tid] = vmax;
}

// ---------------- head -------------------------------------------------------
__global__ void head_k(const float* __restrict__ a1w, const float* __restrict__ a1b,
                       const float* __restrict__ a2w, const float* __restrict__ a2b,
                       float* __restrict__ out) {
    __shared__ float a1s[HIDC*AA];
    __shared__ float a2s[AA*HIDC];
    __shared__ float b1s[HIDC];
    __shared__ float b2s[AA];
    int t = threadIdx.x;
    for (int i = t; i < HIDC*AA; i += blockDim.x) { a1s[i] = a1w[i]; a2s[i] = a2w[i]; }
    for (int i = t; i < HIDC; i += blockDim.x) b1s[i] = a1b[i];
    if (t < AA) b2s[t] = a2b[t];
    __syncthreads();
    int tid = blockIdx.x * blockDim.x + t;
    if (tid >= BB*GG) return;
    int b = tid / GG, pos = tid % GG, y = pos / G, x = pos % G;
    float qv[AA];
    #pragma unroll
    for (int a = 0; a < AA; a++) qv[a] = g_q[(b*AA + a)*HPHP + y*HP + x];
    float lg[AA];
    #pragma unroll
    for (int a = 0; a < AA; a++) lg[a] = 0.f;
    for (int c = 0; c < HIDC; c++) {
        float m = b1s[c];
        #pragma unroll
        for (int a = 0; a < AA; a++) m += qv[a] * a1s[c*AA + a];
        m = fmaxf(m, 0.f);
        #pragma unroll
        for (int a = 0; a < AA; a++) lg[a] += m * a2s[a*HIDC + c];
    }
    #pragma unroll
    for (int a = 0; a < AA; a++) out[(b*AA + a)*GG + pos] = lg[a] + b2s[a];
}

// ---------------- launch -----------------------------------------------------
extern "C" void kernel_launch(void* const* d_in, const int* in_sizes, int n_in,
                              void* d_out, int out_size) {
    const float* grid = (const float*)d_in[0];
    const float* h1w = (const float*)d_in[3];
    const float* h1b = (const float*)d_in[4];
    const float* h2w = (const float*)d_in[5];
    const float* h2b = (const float*)d_in[6];
    const float* rw  = (const float*)d_in[7];
    const float* tw  = (const float*)d_in[8];
    const float* a1w = (const float*)d_in[9];
    const float* a1b = (const float*)d_in[10];
    const float* a2w = (const float*)d_in[11];
    const float* a2b = (const float*)d_in[12];
    float* out = (float*)d_out;

    const int SMEM2  = (4*128*20 + 4*160*20) * 4 + HIDC*4 + 64;  // ~94.4 KB
    const int SMEMRT = (4*128*20 + 4*80*20) * 4 + 64;            // ~66.6 KB
    cudaFuncSetAttribute(mma_conv_k<10, G, 1, GG, 0, 2>,
                         cudaFuncAttributeMaxDynamicSharedMemorySize, SMEM2);
    cudaFuncSetAttribute(mma_conv_k<5, HP, 2, HPHP, 1, 3>,
                         cudaFuncAttributeMaxDynamicSharedMemorySize, SMEMRT);

    prep_k<<<(NCH*160*32 + 255)/256, 256>>>(h2w, rw, tw);
    conv1T_k<<<dim3((GG + 31)/32, BB), 256>>>(grid, h1w, h1b);
    mma_conv_k<10, G, 1, GG, 0, 2><<<dim3((GG + 127)/128, BB), 256, SMEM2>>>(h2b);
    mma_conv_k<5, HP, 2, HPHP, 1, 3><<<dim3((HPHP + 127)/128, BB), 256, SMEMRT>>>(nullptr);
    softmax_k<<<(BB*4*HPHP + 255)/256, 256>>>();
    for (int it = 0; it < KIT; it++)
        vi_step_k<<<(BB*HPHP + 255)/256, 256>>>(it, it == KIT - 1 ? 1 : 0);
    head_k<<<(BB*GG + 255)/256, 256>>>(a1w, a1b, a2w, a2b, out);
}

// round 14
// speedup vs baseline: 2.6807x; 1.0100x over previous
#include <cuda_runtime.h>
#include <cuda_fp16.h>
#include <cstdint>

// Problem constants
#define BB   128
#define CIN  2
#define HIDC 150
#define AA   8
#define KIT  30
#define G    49
#define HP   51
#define GG   (G*G)      // 2401
#define HPHP (HP*HP)    // 2601
#define CPAD 160        // padded channel-last stride (halfs)
#define NCH  46         // chunk count padded to even (last = zero chunk)

// ---------------- scratch (device globals; 16B-aligned) ----------------------
__device__ __align__(16) __half g_hT [BB*GG*CPAD];   // conv1 out, channel-last fp16
__device__ __align__(16) __half g_h2T[BB*GG*CPAD];   // conv2 out, channel-last fp16
__device__ __align__(16) uint32_t g_tru[BB*9*4*HPHP];// softmaxed trans, u16 pairs
__device__ __align__(16) float g_rew [BB*HPHP];
__device__ __align__(16) float g_vbuf[2][BB*HPHP];
__device__ __align__(16) float g_q   [BB*AA*HPHP];
__device__ __align__(16) __half g_wB2 [NCH*160*32];  // conv2 B [s][n][k32] fp16
__device__ __align__(16) __half g_wBrt[NCH*80*32];   // convrt B [s][n][k32] fp16

// ============================ PTX helpers ====================================
__device__ __forceinline__ uint32_t smem_u32(const void* p) {
    uint32_t a;
    asm("{ .reg .u64 t; cvta.to.shared.u64 t, %1; cvt.u32.u64 %0, t; }" : "=r"(a) : "l"(p));
    return a;
}
__device__ __forceinline__ void cpa16(uint32_t dst, const void* src, uint32_t sz) {
    asm volatile("cp.async.cg.shared.global [%0], [%1], 16, %2;"
                 :: "r"(dst), "l"(src), "r"(sz) : "memory");
}
#define CP_COMMIT() asm volatile("cp.async.commit_group;" ::: "memory")
#define CP_WAIT1()  asm volatile("cp.async.wait_group 1;" ::: "memory")
#define CP_WAIT0()  asm volatile("cp.async.wait_group 0;" ::: "memory")
__device__ __forceinline__ void mma16(float* c, const uint32_t* a, const uint32_t* b) {
    asm volatile("mma.sync.aligned.m16n8k16.row.col.f32.f16.f16.f32 "
        "{%0,%1,%2,%3}, {%4,%5,%6,%7}, {%8,%9}, {%0,%1,%2,%3};"
        : "+f"(c[0]), "+f"(c[1]), "+f"(c[2]), "+f"(c[3])
        : "r"(a[0]), "r"(a[1]), "r"(a[2]), "r"(a[3]), "r"(b[0]), "r"(b[1]));
}
__device__ __forceinline__ void ldsm_x4(uint32_t* r, uint32_t addr) {
    asm volatile("ldmatrix.sync.aligned.m8n8.x4.shared.b16 {%0,%1,%2,%3}, [%4];"
        : "=r"(r[0]), "=r"(r[1]), "=r"(r[2]), "=r"(r[3]) : "r"(addr));
}
__device__ __forceinline__ void ldsm_x2(uint32_t* r, uint32_t addr) {
    asm volatile("ldmatrix.sync.aligned.m8n8.x2.shared.b16 {%0,%1}, [%2];"
        : "=r"(r[0]), "=r"(r[1]) : "r"(addr));
}

// ---------------- weight prep: fp16 B tiles [s][n][k(32)], s<45 real ---------
__global__ void prep_k(const float* __restrict__ h2w,
                       const float* __restrict__ rw,
                       const float* __restrict__ tw) {
    int i = blockIdx.x * blockDim.x + threadIdx.x;
    if (i < NCH*160*32) {
        int k = i & 31, n = (i >> 5) % 160, s = i / (160*32);
        float v = 0.f;
        if (s < 45) {
            int tap = s/5, ci = (s%5)*32 + k;
            if (n < HIDC && ci < HIDC) v = h2w[(n*HIDC + ci)*9 + tap];
        }
        g_wB2[i] = __float2half_rn(v);
    }
    if (i < NCH*80*32) {
        int k = i & 31, n = (i >> 5) % 80, s = i / (80*32);
        float v = 0.f;
        if (s < 45) {
            int tap = s/5, ci = (s%5)*32 + k;
            if (ci < HIDC) {
                if (n == 0)      v = rw[ci*9 + tap];
                else if (n < 73) v = tw[((n-1)*HIDC + ci)*9 + tap];
            }
        }
        g_wBrt[i] = __float2half_rn(v);
    }
}

// -------- conv1 fused with channel-last transpose: grid -> g_hT (fp16) -------
__global__ void conv1T_k(const float* __restrict__ gin,
                         const float* __restrict__ w,
                         const float* __restrict__ bias) {
    __shared__ float ws[HIDC*CIN*9];
    __shared__ float bs[HIDC];
    __shared__ __align__(16) __half tile[32*176];
    int t = threadIdx.x;
    for (int i = t; i < HIDC*CIN*9; i += 256) ws[i] = w[i];
    for (int i = t; i < HIDC; i += 256) bs[i] = bias[i];
    __syncthreads();
    int pos0 = blockIdx.x * 32, b = blockIdx.y;
    int posi = t & 31, colane = t >> 5;
    int pos = pos0 + posi;
    bool okp = pos < GG;
    int y = okp ? pos / G : 0, x = okp ? pos % G : 0;
    float gv[CIN][9];
    #pragma unroll
    for (int ci = 0; ci < CIN; ci++)
        #pragma unroll
        for (int k = 0; k < 9; k++) {
            int r = y + k/3 - 1, c = x + k%3 - 1;
            gv[ci][k] = (okp && r >= 0 && r < G && c >= 0 && c < G)
                        ? gin[(b*CIN + ci)*GG + r*G + c] : 0.f;
        }
    #pragma unroll
    for (int j = 0; j < 20; j++) {
        int co = colane + 8*j;
        float out = 0.f;
        if (co < HIDC) {
            float acc = bs[co];
            #pragma unroll
            for (int ci = 0; ci < CIN; ci++)
                #pragma unroll
                for (int k = 0; k < 9; k++)
                    acc += gv[ci][k] * ws[(co*CIN + ci)*9 + k];
            out = fmaxf(acc, 0.f);
        }
        tile[posi*176 + co] = __float2half_rn(out);
    }
    __syncthreads();
    #pragma unroll
    for (int j = 0; j < 3; j++) {
        int qi = t + 256*j;
        if (qi < 640) {
            int row = qi / 20, q = qi - row*20;
            if (pos0 + row < GG) {
                *(uint4*)&g_hT[((size_t)(b*GG + pos0 + row))*CPAD + q*8] =
                    *(const uint4*)&tile[row*176 + q*8];
            }
        }
    }
}

// ========= fp16 mma.sync m16n8k16 implicit-GEMM conv, ldmatrix fragments =====
// Slot = 2 consecutive K=32 chunks. Fragments via LDSM (x4/x2).
// MODE 0: conv2 (g_hT -> relu+bias -> g_h2T fp16), NFRAG=10 (N=160)
// MODE 1: convrt (g_h2T -> g_rew + FUSED softmax -> g_tru), NFRAG=5 (N=80)
template<int NFRAG, int OW, int PADC, int PTOT, int MODE, int MINB>
__global__ void __launch_bounds__(256, MINB) mma_conv_k(const float* __restrict__ bias) {
    constexpr int NOUT_PAD = NFRAG * 16;
    constexpr int RSTR = 20;                        // b32 per row
    constexpr int AW = 128 * RSTR;                  // b32 per A chunk (2560)
    constexpr int BW = NOUT_PAD * RSTR;             // b32 per B chunk
    constexpr int ASLOT = 2*AW, BSLOT = 2*BW;       // slot = chunk pair
    constexpr int BQN = NOUT_PAD * 4;               // quads per B chunk
    constexpr int NPAIR = NFRAG/2;
    constexpr bool ODD = (NFRAG & 1) != 0;
    extern __shared__ __align__(16) uint32_t smu[];
    float* biasS = (float*)(smu + 2*ASLOT + 2*BSLOT);
    const __half* inH = (MODE == 0) ? g_hT : g_h2T;
    const __half* wB  = (MODE == 0) ? g_wB2 : g_wBrt;

    int t = threadIdx.x;
    int b = blockIdx.y, tile0 = blockIdx.x * 128;
    uint32_t smb = smem_u32(smu);

    if (MODE == 0) for (int i = t; i < HIDC; i += 256) biasS[i] = bias[i];

    // A-load invariants: thread covers rows (t>>2) and (t>>2)+64, quad t&3
    const int aq = t & 3;
    int yy[2], xx[2];
    uint32_t dA[2];
    #pragma unroll
    for (int i = 0; i < 2; i++) {
        int row = (t >> 2) + 64*i;
        int pos = tile0 + row;
        yy[i] = pos / OW;
        xx[i] = pos - yy[i]*OW;
        dA[i] = (uint32_t)(row*RSTR*4 + aq*16);
    }
    const __half* inB = inH + (size_t)b*GG*CPAD + aq*8;

    // load one pair of chunks (2p, 2p+1) into slot; single commit
    auto load_pair = [&](int p, int slot) {
        #pragma unroll
        for (int j = 0; j < 2; j++) {
            int s = 2*p + j;
            int tap = s / 5, cc = s - tap*5;
            int dyp = tap/3 - PADC, dxp = tap%3 - PADC, ci0 = cc*32;
            bool real = (s < 45);
            uint32_t Ab = smb + (uint32_t)(slot*ASLOT + j*AW)*4;
            #pragma unroll
            for (int i = 0; i < 2; i++) {
                int ir = yy[i] + dyp, ic = xx[i] + dxp;
                bool ok = real && ((unsigned)ir < G) && ((unsigned)ic < G);
                const __half* src = inB + (size_t)(ok ? (ir*G + ic) : 0)*CPAD + ci0;
                cpa16(Ab + dA[i], src, ok ? 16u : 0u);
            }
            uint32_t Bb = smb + (uint32_t)(2*ASLOT + slot*BSLOT + j*BW)*4;
            const __half* wsrc = wB + (size_t)s*NOUT_PAD*32;
            #pragma unroll
            for (int jj = 0; jj < (BQN + 255)/256; jj++) {
                int qi = t + 256*jj;
                if (qi < BQN) {
                    int n = qi >> 2, q = qi & 3;
                    cpa16(Bb + (uint32_t)(n*RSTR*4 + q*16), wsrc + n*32 + q*8, 16u);
                }
            }
        }
        CP_COMMIT();
    };

    const int lane = t & 31, wid = t >> 5;
    const int gid = lane >> 2, tig = lane & 3;
    const int m0w = (wid >> 1) * 32, n0w = (wid & 1) * NFRAG * 8;

    // ldmatrix per-thread byte offsets (invariant; add buffer base at use)
    uint32_t aoff[2][2];
    #pragma unroll
    for (int mf = 0; mf < 2; mf++)
        #pragma unroll
        for (int ks = 0; ks < 2; ks++)
            aoff[mf][ks] = (uint32_t)(((m0w + mf*16 + (lane & 15))*RSTR
                                       + ks*8 + (lane >> 4)*4) * 4);
    uint32_t boff[(NPAIR > 0 ? NPAIR : 1)][2];
    #pragma unroll
    for (int pr = 0; pr < NPAIR; pr++)
        #pragma unroll
        for (int ks = 0; ks < 2; ks++)
            boff[pr][ks] = (uint32_t)(((n0w + pr*16 + ((lane >> 4) << 3) + (lane & 7))*RSTR
                                       + ks*8 + (((lane >> 3) & 1) << 2)) * 4);
    uint32_t boff2[2];
    #pragma unroll
    for (int ks = 0; ks < 2; ks++)
        boff2[ks] = (uint32_t)(((n0w + (NFRAG-1)*8 + (lane & 7))*RSTR
                                + ks*8 + ((((lane & 15) >> 3) & 1) << 2)) * 4);

    float c[2][NFRAG][4];
    #pragma unroll
    for (int mf = 0; mf < 2; mf++)
        #pragma unroll
        for (int nf = 0; nf < NFRAG; nf++)
            #pragma unroll
            for (int e = 0; e < 4; e++) c[mf][nf][e] = 0.f;

    constexpr int NP = NCH/2;     // 23 pairs
    load_pair(0, 0);
    for (int p = 0; p < NP; p++) {
        int cur = p & 1;
        if (p < NP-1) { load_pair(p + 1, cur ^ 1); CP_WAIT1(); }
        else          { CP_WAIT0(); }
        __syncthreads();
        #pragma unroll
        for (int j = 0; j < 2; j++) {
            uint32_t Abase = smb + (uint32_t)(cur*ASLOT + j*AW)*4;
            uint32_t Bbase = smb + (uint32_t)(2*ASLOT + cur*BSLOT + j*BW)*4;
            #pragma unroll
            for (int ks = 0; ks < 2; ks++) {
                uint32_t a[2][4];
                ldsm_x4(a[0], Abase + aoff[0][ks]);
                ldsm_x4(a[1], Abase + aoff[1][ks]);
                uint32_t bv[NFRAG][2];
                #pragma unroll
                for (int pr = 0; pr < NPAIR; pr++) {
                    uint32_t r4[4];
                    ldsm_x4(r4, Bbase + boff[pr][ks]);
                    bv[2*pr][0] = r4[0]; bv[2*pr][1] = r4[1];
                    bv[2*pr+1][0] = r4[2]; bv[2*pr+1][1] = r4[3];
                }
                if (ODD) ldsm_x2(bv[NFRAG-1], Bbase + boff2[ks]);
                #pragma unroll
                for (int nf = 0; nf < NFRAG; nf++) {
                    mma16(c[0][nf], a[0], bv[nf]);
                    mma16(c[1][nf], a[1], bv[nf]);
                }
            }
        }
        __syncthreads();
    }

    // ---- epilogue ----
    if (MODE == 0) {
        #pragma unroll
        for (int mf = 0; mf < 2; mf++) {
            #pragma unroll
            for (int rr = 0; rr < 2; rr++) {
                int pos = tile0 + m0w + mf*16 + gid + rr*8;
                if (pos >= PTOT) continue;
                __half* op = &g_h2T[((size_t)(b*GG + pos))*CPAD];
                #pragma unroll
                for (int nf = 0; nf < NFRAG; nf++) {
                    int co = n0w + nf*8 + 2*tig;
                    float v0 = c[mf][nf][rr*2 + 0], v1 = c[mf][nf][rr*2 + 1];
                    float o0 = (co   < HIDC) ? fmaxf(v0 + biasS[co],   0.f) : 0.f;
                    float o1 = (co+1 < HIDC) ? fmaxf(v1 + biasS[co+1], 0.f) : 0.f;
                    *(__half2*)&op[co] = __floats2half2_rn(o0, o1);
                }
            }
        }
    } else {
        // ---- fused softmax epilogue: regs -> smem qbuf -> u16 g_tru ----
        float* qbuf = (float*)smu;                 // 128 x 80 fp32 = 40 KB (aliases stages)
        #pragma unroll
        for (int mf = 0; mf < 2; mf++) {
            #pragma unroll
            for (int rr = 0; rr < 2; rr++) {
                int m = m0w + mf*16 + gid + rr*8;  // local row 0..127
                #pragma unroll
                for (int nf = 0; nf < NFRAG; nf++) {
                    int co = n0w + nf*8 + 2*tig;
                    float2 v = make_float2(c[mf][nf][rr*2 + 0], c[mf][nf][rr*2 + 1]);
                    *(float2*)&qbuf[m*80 + co] = v;
                }
            }
        }
        __syncthreads();
        // 512 tasks: (pos_l 0..127) x (a2 0..3)
        #pragma unroll
        for (int task = t; task < 512; task += 256) {
            int pos_l = task & 127, a2 = task >> 7;
            int pos = tile0 + pos_l;
            if (pos >= HPHP) continue;
            const float* qr = &qbuf[pos_l*80];
            if (a2 == 0) g_rew[b*HPHP + pos] = qr[0];
            float v0[9], v1[9];
            float mx0 = -1e30f, mx1 = -1e30f;
            #pragma unroll
            for (int k = 0; k < 9; k++) {
                v0[k] = qr[1 + 18*a2 + k];     mx0 = fmaxf(mx0, v0[k]);
                v1[k] = qr[1 + 18*a2 + 9 + k]; mx1 = fmaxf(mx1, v1[k]);
            }
            float s0 = 0.f, s1 = 0.f;
            #pragma unroll
            for (int k = 0; k < 9; k++) {
                v0[k] = expf(v0[k] - mx0); s0 += v0[k];
                v1[k] = expf(v1[k] - mx1); s1 += v1[k];
            }
            float i0 = 65536.f / s0, i1 = 65536.f / s1;
            #pragma unroll
            for (int k = 0; k < 9; k++) {
                float y0 = fmaf(v0[k], i0, 8388608.f);
                float y1 = fmaf(v1[k], i1, 8388608.f);
                uint32_t pk = __byte_perm(__float_as_uint(y0), __float_as_uint(y1), 0x5410);
                g_tru[((size_t)(b*9 + k)*4 + a2)*HPHP + pos] = pk;
            }
        }
    }
}

// ---------------- one value-iteration step (u16 trans) -----------------------
__global__ void vi_step_k(int iter, int store_q) {
    int tid = blockIdx.x * blockDim.x + threadIdx.x;
    if (tid >= BB*HPHP) return;
    int b = tid / HPHP, pos = tid - b*HPHP, y = pos / HP, x = pos - y*HP;
    const float* vin = g_vbuf[(iter & 1) ^ 1];
    float p[9];
    if (iter == 0) {
        #pragma unroll
        for (int k = 0; k < 9; k++) p[k] = 0.f;
    } else {
        #pragma unroll
        for (int k = 0; k < 9; k++) {
            int r = y + k/3 - 1, c = x + k%3 - 1;
            p[k] = (r >= 0 && r < HP && c >= 0 && c < HP)
                   ? vin[b*HPHP + r*HP + c] : 0.f;
        }
    }
    float r0 = g_rew[tid];
    float vmax = -1e30f;
    const uint32_t* trb = g_tru + (size_t)b*36*HPHP + pos;
    #pragma unroll
    for (int a2 = 0; a2 < 4; a2++) {
        float q0 = r0, q1 = r0;
        #pragma unroll
        for (int k = 0; k < 9; k++) {
            uint32_t w = trb[(size_t)(k*4 + a2)*HPHP];
            float f0 = __uint_as_float(__byte_perm(w, 0x4B000000u, 0x7410));
            float f1 = __uint_as_float(__byte_perm(w, 0x4B000000u, 0x7432));
            float P0 = fmaf(f0, 1.f/65536.f, -128.f);
            float P1 = fmaf(f1, 1.f/65536.f, -128.f);
            q0 = fmaf(P0, p[k], q0);
            q1 = fmaf(P1, p[k], q1);
        }
        if (store_q) {
            g_q[(b*AA + 2*a2    )*HPHP + pos] = q0;
            g_q[(b*AA + 2*a2 + 1)*HPHP + pos] = q1;
        }
        vmax = fmaxf(fmaxf(q0, q1), vmax);
    }
    g_vbuf[iter & 1][tid] = vmax;
}

// ---------------- head -------------------------------------------------------
__global__ void head_k(const float* __restrict__ a1w, const float* __restrict__ a1b,
                       const float* __restrict__ a2w, const float* __restrict__ a2b,
                       float* __restrict__ out) {
    __shared__ float a1s[HIDC*AA];
    __shared__ float a2s[AA*HIDC];
    __shared__ float b1s[HIDC];
    __shared__ float b2s[AA];
    int t = threadIdx.x;
    for (int i = t; i < HIDC*AA; i += blockDim.x) { a1s[i] = a1w[i]; a2s[i] = a2w[i]; }
    for (int i = t; i < HIDC; i += blockDim.x) b1s[i] = a1b[i];
    if (t < AA) b2s[t] = a2b[t];
    __syncthreads();
    int tid = blockIdx.x * blockDim.x + t;
    if (tid >= BB*GG) return;
    int b = tid / GG, pos = tid % GG, y = pos / G, x = pos % G;
    float qv[AA];
    #pragma unroll
    for (int a = 0; a < AA; a++) qv[a] = g_q[(b*AA + a)*HPHP + y*HP + x];
    float lg[AA];
    #pragma unroll
    for (int a = 0; a < AA; a++) lg[a] = 0.f;
    for (int c = 0; c < HIDC; c++) {
        float m = b1s[c];
        #pragma unroll
        for (int a = 0; a < AA; a++) m += qv[a] * a1s[c*AA + a];
        m = fmaxf(m, 0.f);
        #pragma unroll
        for (int a = 0; a < AA; a++) lg[a] += m * a2s[a*HIDC + c];
    }
    #pragma unroll
    for (int a = 0; a < AA; a++) out[(b*AA + a)*GG + pos] = lg[a] + b2s[a];
}

// ---------------- launch -----------------------------------------------------
extern "C" void kernel_launch(void* const* d_in, const int* in_sizes, int n_in,
                              void* d_out, int out_size) {
    const float* grid = (const float*)d_in[0];
    const float* h1w = (const float*)d_in[3];
    const float* h1b = (const float*)d_in[4];
    const float* h2w = (const float*)d_in[5];
    const float* h2b = (const float*)d_in[6];
    const float* rw  = (const float*)d_in[7];
    const float* tw  = (const float*)d_in[8];
    const float* a1w = (const float*)d_in[9];
    const float* a1b = (const float*)d_in[10];
    const float* a2w = (const float*)d_in[11];
    const float* a2b = (const float*)d_in[12];
    float* out = (float*)d_out;

    const int SMEM2  = (4*128*20 + 4*160*20) * 4 + HIDC*4 + 64;  // ~94.4 KB
    const int SMEMRT = (4*128*20 + 4*80*20) * 4 + 64;            // ~66.6 KB (>= 40KB qbuf)
    cudaFuncSetAttribute(mma_conv_k<10, G, 1, GG, 0, 2>,
                         cudaFuncAttributeMaxDynamicSharedMemorySize, SMEM2);
    cudaFuncSetAttribute(mma_conv_k<5, HP, 2, HPHP, 1, 3>,
                         cudaFuncAttributeMaxDynamicSharedMemorySize, SMEMRT);

    prep_k<<<(NCH*160*32 + 255)/256, 256>>>(h2w, rw, tw);
    conv1T_k<<<dim3((GG + 31)/32, BB), 256>>>(grid, h1w, h1b);
    mma_conv_k<10, G, 1, GG, 0, 2><<<dim3((GG + 127)/128, BB), 256, SMEM2>>>(h2b);
    mma_conv_k<5, HP, 2, HPHP, 1, 3><<<dim3((HPHP + 127)/128, BB), 256, SMEMRT>>>(nullptr);
    for (int it = 0; it < KIT; it++)
        vi_step_k<<<(BB*HPHP + 255)/256, 256>>>(it, it == KIT - 1 ? 1 : 0);
    head_k<<<(BB*GG + 255)/256, 256>>>(a1w, a1b, a2w, a2b, out);
}